// round 1
// baseline (speedup 1.0000x reference)
#include <cuda_runtime.h>
#include <math.h>

// Problem constants
#define WD   127          // 2*W-1 diagonal steps
#define NB   16           // batch
#define NH   64           // height
#define NW   64           // width
#define NC   256          // channels (CIN == COUT)
#define MROWS 2048        // 2 dirs * B * H rows packed
#define NGO  1024         // 4*NC gate outputs (permuted go' = co*4 + gate)
#define KDIM 512          // [h_prev | h_next] concat

// ---------------- persistent device scratch (no allocation allowed) ----------------
__device__ float d_Y[NB * NH * NW * NGO];     // [b*4096 + h*64 + w][go']  (268 MB)
__device__ float d_hs[WD * MROWS * NC];       // per-step hidden outputs   (266 MB)
__device__ float d_Hst[2][MROWS * NC];        // ping-pong hidden state
__device__ float d_Cst[MROWS * NC];           // cell state (in-place)
__device__ float d_AcatT[KDIM * NGO];         // K-major fused recurrence weights
__device__ float d_W2T[NC * NGO];             // K-major fused input weights
__device__ float d_biasT[NGO];                // fused bias (permuted)

// go' = co*4 + g  <->  go = g*256 + co
__device__ __forceinline__ int go_of_gp(int gp) { return (gp & 3) * 256 + (gp >> 2); }

// ---------------- prep kernels ----------------

// AcatT[k][gp] = sum_c w_ih[go(gp)][c] * (k<256 ? k0 : k1)[c][k%256]
__global__ void prep_A(const float* __restrict__ w_ih,
                       const float* __restrict__ k0,
                       const float* __restrict__ k1) {
    __shared__ float Wt[32][33];  // [cc][gp_l]
    __shared__ float Ks[32][33];  // [cc][k_l]
    int x = threadIdx.x, y = threadIdx.y;
    int gp0 = blockIdx.x * 32;
    int kb0 = blockIdx.y * 32;
    const float* ksel = (kb0 < 256) ? k0 : k1;
    int j0 = kb0 & 255;
    float acc = 0.f;
    for (int c0 = 0; c0 < 256; c0 += 32) {
        int go = go_of_gp(gp0 + y);
        Wt[x][y] = w_ih[go * 256 + c0 + x];          // coalesced in x
        Ks[y][x] = ksel[(c0 + y) * 256 + j0 + x];    // coalesced in x
        __syncthreads();
#pragma unroll
        for (int cc = 0; cc < 32; cc++)
            acc += Wt[cc][x] * Ks[cc][y];
        __syncthreads();
    }
    d_AcatT[(kb0 + y) * NGO + gp0 + x] = acc;
}

// W2T[ci][gp] = sum_c w_ih[go(gp)][c] * w_i2s[c][ci] * (ci%3 <= c%3)
__global__ void prep_W2(const float* __restrict__ w_ih,
                        const float* __restrict__ w_i2s) {
    __shared__ float Wt[32][33];  // [cc][gp_l]
    __shared__ float Ms[32][33];  // [cc][ci_l]
    int x = threadIdx.x, y = threadIdx.y;
    int gp0 = blockIdx.x * 32;
    int ci0 = blockIdx.y * 32;
    float acc = 0.f;
    for (int c0 = 0; c0 < 256; c0 += 32) {
        int go = go_of_gp(gp0 + y);
        Wt[x][y] = w_ih[go * 256 + c0 + x];
        int ci = ci0 + x, c = c0 + y;
        float m = ((ci % 3) <= (c % 3)) ? 1.f : 0.f;
        Ms[y][x] = w_i2s[c * 256 + ci] * m;
        __syncthreads();
#pragma unroll
        for (int cc = 0; cc < 32; cc++)
            acc += Wt[cc][x] * Ms[cc][y];
        __syncthreads();
    }
    d_W2T[(ci0 + y) * NGO + gp0 + x] = acc;
}

// biasT[gp] = b_ih[go] + b_hh[go] + sum_c w_ih[go][c]*(b_i2s[c] + b_s2s[c])
__global__ void prep_bias(const float* __restrict__ w_ih,
                          const float* __restrict__ b_ih,
                          const float* __restrict__ b_hh,
                          const float* __restrict__ b_i2s,
                          const float* __restrict__ b_s2s) {
    int gp = threadIdx.x;  // 1024 threads
    int go = go_of_gp(gp);
    float s = b_ih[go] + b_hh[go];
    for (int c = 0; c < 256; c++)
        s += w_ih[go * 256 + c] * (b_i2s[c] + b_s2s[c]);
    d_biasT[gp] = s;
}

__global__ void init_state() {
    int i = blockIdx.x * blockDim.x + threadIdx.x;
    if (i < MROWS * NC) { d_Hst[0][i] = 0.f; d_Cst[i] = 0.f; }
}

// ---------------- Y GEMM: Y[bhw][gp] = sum_ci x[b][ci][hw] * W2T[ci][gp] ----------------
__global__ __launch_bounds__(256) void ygemm(const float* __restrict__ x) {
    __shared__ float Xs[32 * 68];   // [ci_l][row_l]  (pad 68)
    __shared__ float As[32 * 128];  // [ci_l][col_l]
    int tid = threadIdx.x;
    int tx = tid & 31, ty = tid >> 5;
    int r0 = blockIdx.y * 64;       // bhw
    int n0 = blockIdx.x * 128;      // go'
    int b = r0 >> 12, hw0 = r0 & 4095;
    float acc[8][4] = {};
    for (int k0 = 0; k0 < 256; k0 += 32) {
#pragma unroll
        for (int it = 0; it < 8; it++) {
            int e = it * 256 + tid;
            int kk = e >> 6, rr = e & 63;
            Xs[kk * 68 + rr] = x[(b * 256 + k0 + kk) * 4096 + hw0 + rr];
        }
#pragma unroll
        for (int it = 0; it < 16; it++) {
            int e = it * 256 + tid;
            int cc = e & 127, kk = e >> 7;
            As[kk * 128 + cc] = d_W2T[(k0 + kk) * NGO + n0 + cc];
        }
        __syncthreads();
#pragma unroll
        for (int kk = 0; kk < 32; kk++) {
            float4 a  = *(const float4*)&As[kk * 128 + tx * 4];
            float4 h0 = *(const float4*)&Xs[kk * 68 + ty * 8];
            float4 h1 = *(const float4*)&Xs[kk * 68 + ty * 8 + 4];
            float hr[8] = {h0.x, h0.y, h0.z, h0.w, h1.x, h1.y, h1.z, h1.w};
            float ar[4] = {a.x, a.y, a.z, a.w};
#pragma unroll
            for (int i = 0; i < 8; i++)
#pragma unroll
                for (int g = 0; g < 4; g++)
                    acc[i][g] += hr[i] * ar[g];
        }
        __syncthreads();
    }
#pragma unroll
    for (int i = 0; i < 8; i++) {
        float4 v = {acc[i][0], acc[i][1], acc[i][2], acc[i][3]};
        *(float4*)&d_Y[(size_t)(r0 + ty * 8 + i) * NGO + n0 + tx * 4] = v;
    }
}

// ---------------- per-step fused GEMM + LSTM cell ----------------
// gates[r][gp] = bias + Y_gather + sum_k Hcat[r][k]*AcatT[k][gp]
// Hcat[r][k]: k<256 -> H[r][k];  k>=256 -> H[r+1][k-256] (0 at dir boundary)
__global__ __launch_bounds__(256) void step_kernel(int t) {
    __shared__ float Hs[32 * 68];   // [k_l][row_l]
    __shared__ float As[32 * 128];  // [k_l][col_l]
    const float* Hin  = d_Hst[t & 1];
    float*       Hout = d_Hst[(t + 1) & 1];
    int tid = threadIdx.x;
    int tx = tid & 31, ty = tid >> 5;
    int r0 = blockIdx.y * 64;   // row base
    int n0 = blockIdx.x * 128;  // go' base
    float acc[8][4] = {};
    for (int k0 = 0; k0 < KDIM; k0 += 32) {
        bool second = (k0 >= 256);
        int kc = second ? (k0 - 256) : k0;
#pragma unroll
        for (int it = 0; it < 8; it++) {
            int e = it * 256 + tid;
            int kk = e & 31, rr = e >> 5;
            int r = r0 + rr;
            float v;
            if (second) {
                v = ((r & 1023) == 1023) ? 0.f : Hin[(r + 1) * NC + kc + kk];
            } else {
                v = Hin[r * NC + kc + kk];
            }
            Hs[kk * 68 + rr] = v;
        }
#pragma unroll
        for (int it = 0; it < 16; it++) {
            int e = it * 256 + tid;
            int cc = e & 127, kk = e >> 7;
            As[kk * 128 + cc] = d_AcatT[(k0 + kk) * NGO + n0 + cc];
        }
        __syncthreads();
#pragma unroll
        for (int kk = 0; kk < 32; kk++) {
            float4 a  = *(const float4*)&As[kk * 128 + tx * 4];
            float4 h0 = *(const float4*)&Hs[kk * 68 + ty * 8];
            float4 h1 = *(const float4*)&Hs[kk * 68 + ty * 8 + 4];
            float hr[8] = {h0.x, h0.y, h0.z, h0.w, h1.x, h1.y, h1.z, h1.w};
            float ar[4] = {a.x, a.y, a.z, a.w};
#pragma unroll
            for (int i = 0; i < 8; i++)
#pragma unroll
                for (int g = 0; g < 4; g++)
                    acc[i][g] += hr[i] * ar[g];
        }
        __syncthreads();
    }
    // epilogue: LSTM cell (thread owns 4 consecutive gp = gates i,f,g,o of one co)
    int gp = n0 + tx * 4;
    int co = gp >> 2;
    float4 bias = *(const float4*)&d_biasT[gp];
#pragma unroll
    for (int i = 0; i < 8; i++) {
        int r = r0 + ty * 8 + i;
        int dir = r >> 10, bh = r & 1023;
        int b = bh >> 6, hh = bh & 63;
        int d = t - hh;
        float4 yv = {0.f, 0.f, 0.f, 0.f};
        if (d >= 0 && d < 64) {
            int w = dir ? (63 - d) : d;
            yv = *(const float4*)&d_Y[(size_t)((b * 64 + hh) * 64 + w) * NGO + gp];
        }
        float gi = acc[i][0] + bias.x + yv.x;
        float gf = acc[i][1] + bias.y + yv.y;
        float gg = acc[i][2] + bias.z + yv.z;
        float go = acc[i][3] + bias.w + yv.w;
        float si = 1.f / (1.f + expf(-gi));
        float sf = 1.f / (1.f + expf(-gf));
        float so = 1.f / (1.f + expf(-go));
        float cn = sf * d_Cst[r * NC + co] + si * tanhf(gg);
        float h  = so * tanhf(cn);
        d_Cst[r * NC + co] = cn;
        Hout[r * NC + co]  = h;
        d_hs[((size_t)t * MROWS + r) * NC + co] = h;
    }
}

// ---------------- output assembly: unskew + faithful reshape + bidir combine ----------------
// left [b,c2,h2,w] = hs[h2+w][b*64 + (c2>>2)][(c2&3)*64 + h2]           (dir 0)
// right[b,c2,h2,w] = h2==0 ? 0 : hs[h2+62-w][1024 + b*64 + (c2>>2)][(c2&3)*64 + h2-1]
__global__ __launch_bounds__(256) void output_kernel(float* __restrict__ out) {
    __shared__ float tile[127 * 65];
    int c2 = blockIdx.x, b = blockIdx.y;
    int tid = threadIdx.x;
    int hi  = c2 >> 2;
    int coL = (c2 & 3) * 64;
    int rL  = b * 64 + hi;
    for (int e = tid; e < 127 * 64; e += 256) {
        int tt = e >> 6, j = e & 63;
        tile[tt * 65 + j] = d_hs[((size_t)tt * MROWS + rL) * NC + coL + j];
    }
    __syncthreads();
    float rl[16];
#pragma unroll
    for (int it = 0; it < 16; it++) {
        int o = it * 256 + tid;
        int h2 = o >> 6, w = o & 63;
        rl[it] = tile[(h2 + w) * 65 + h2];
    }
    __syncthreads();
    int rR = 1024 + b * 64 + hi;
    for (int e = tid; e < 127 * 64; e += 256) {
        int tt = e >> 6, j = e & 63;
        tile[tt * 65 + j] = d_hs[((size_t)tt * MROWS + rR) * NC + coL + j];
    }
    __syncthreads();
    float* ob = out + ((size_t)(b * 256 + c2)) * 64 * 64;
#pragma unroll
    for (int it = 0; it < 16; it++) {
        int o = it * 256 + tid;
        int h2 = o >> 6, w = o & 63;
        float rv = (h2 > 0) ? tile[(h2 + 62 - w) * 65 + (h2 - 1)] : 0.f;
        ob[o] = rl[it] + rv;
    }
}

// ---------------- launch ----------------
extern "C" void kernel_launch(void* const* d_in, const int* in_sizes, int n_in,
                              void* d_out, int out_size) {
    const float* x     = (const float*)d_in[0];
    const float* w_i2s = (const float*)d_in[1];
    const float* b_i2s = (const float*)d_in[2];
    const float* w_ih  = (const float*)d_in[3];
    const float* b_ih  = (const float*)d_in[4];
    const float* b_hh  = (const float*)d_in[5];
    const float* k0    = (const float*)d_in[6];
    const float* k1    = (const float*)d_in[7];
    const float* b_s2s = (const float*)d_in[8];
    float* out = (float*)d_out;

    prep_A  <<<dim3(32, 16), dim3(32, 32)>>>(w_ih, k0, k1);
    prep_W2 <<<dim3(32,  8), dim3(32, 32)>>>(w_ih, w_i2s);
    prep_bias<<<1, 1024>>>(w_ih, b_ih, b_hh, b_i2s, b_s2s);
    init_state<<<(MROWS * NC + 255) / 256, 256>>>();
    ygemm<<<dim3(8, 1024), 256>>>(x);

    for (int t = 0; t < WD; t++)
        step_kernel<<<dim3(8, 32), 256>>>(t);

    output_kernel<<<dim3(256, 16), 256>>>(out);
}

// round 6
// speedup vs baseline: 1.4761x; 1.4761x over previous
#include <cuda_runtime.h>
#include <cuda_bf16.h>
#include <math.h>
#include <stdint.h>

// ---------------- problem constants ----------------
#define WD    127
#define NB    16
#define NH    64
#define NW    64
#define NC    256
#define MROWS 2048
#define NGO   1024
#define YROWS 65536        // NB*NH*NW
#define KK_STEP 1536       // 3 * 512 (hi/lo split in K)
#define KK_Y    768        // 3 * 256
#define NCH_STEP 24        // KK_STEP / 64
#define NCH_Y    12        // KK_Y / 64
#define LDS_H   72         // smem row stride in halves (144B, 16B-aligned, conflict-free)
#define STAGE_H (128 * LDS_H)
#define SMEM_BYTES (4 * STAGE_H * 2)   // 2 ops x 2 stages x 18432B = 73728

// ---------------- persistent device scratch ----------------
__device__ __align__(128) float d_Y[(size_t)YROWS * NGO];
__device__ __align__(128) float d_hs[(size_t)WD * MROWS * NC];
__device__ __align__(128) float d_Cst[MROWS * NC];
__device__ __align__(128) __nv_bfloat16 d_Hhi[2][MROWS * NC];
__device__ __align__(128) __nv_bfloat16 d_Hlo[2][MROWS * NC];
__device__ __align__(128) float d_AcatT[512 * NGO];
__device__ __align__(128) float d_W2T[256 * NGO];
__device__ __align__(128) float d_biasT[NGO];
__device__ __align__(128) __nv_bfloat16 d_Wb[NGO * KK_STEP];   // [gp][kk] segs hi|hi|lo
__device__ __align__(128) __nv_bfloat16 d_W2b[NGO * KK_Y];     // [gp][kk]
__device__ __align__(128) __nv_bfloat16 d_Xb[(size_t)YROWS * 512]; // [r][0:256)=hi,[256:512)=lo

__device__ __forceinline__ int go_of_gp(int gp) { return (gp & 3) * 256 + (gp >> 2); }

// ---------------- baseline-PTX helpers (compile under compute_103) ----------------
__device__ __forceinline__ uint32_t smem_u32(const void* p) {
    uint32_t a;
    asm("{ .reg .u64 t; cvta.to.shared.u64 t, %1; cvt.u32.u64 %0, t; }" : "=r"(a) : "l"(p));
    return a;
}
__device__ __forceinline__ void cp16(uint32_t dst, const void* src, bool pred) {
    int sz = pred ? 16 : 0;
    asm volatile("cp.async.cg.shared.global [%0], [%1], 16, %2;"
                 :: "r"(dst), "l"(src), "r"(sz) : "memory");
}
__device__ __forceinline__ void cp_commit() { asm volatile("cp.async.commit_group;" ::: "memory"); }
template <int N>
__device__ __forceinline__ void cp_wait() { asm volatile("cp.async.wait_group %0;" :: "n"(N) : "memory"); }

__device__ __forceinline__ void ldm_x4(uint32_t* r, uint32_t addr) {
    asm volatile("ldmatrix.sync.aligned.m8n8.x4.shared.b16 {%0,%1,%2,%3}, [%4];"
                 : "=r"(r[0]), "=r"(r[1]), "=r"(r[2]), "=r"(r[3]) : "r"(addr));
}
__device__ __forceinline__ void mma16816(float* c, const uint32_t* a, const uint32_t* b) {
    asm volatile("mma.sync.aligned.m16n8k16.row.col.f32.bf16.bf16.f32 "
                 "{%0,%1,%2,%3}, {%4,%5,%6,%7}, {%8,%9}, {%0,%1,%2,%3};"
                 : "+f"(c[0]), "+f"(c[1]), "+f"(c[2]), "+f"(c[3])
                 : "r"(a[0]), "r"(a[1]), "r"(a[2]), "r"(a[3]), "r"(b[0]), "r"(b[1]));
}
__device__ __forceinline__ float fast_tanh(float x) {
    x = fminf(fmaxf(x, -15.f), 15.f);   // guard __expf overflow -> NaN
    float e = __expf(2.f * x);
    return (e - 1.f) / (e + 1.f);
}
__device__ __forceinline__ float fast_sig(float x) { return 1.f / (1.f + __expf(-x)); }

extern __shared__ __align__(1024) __nv_bfloat16 smem[];

// ---------------- prep kernels (fp32 weight fusion) ----------------
__global__ void prep_A(const float* __restrict__ w_ih,
                       const float* __restrict__ k0,
                       const float* __restrict__ k1) {
    __shared__ float Wt[32][33];
    __shared__ float Ks[32][33];
    int x = threadIdx.x, y = threadIdx.y;
    int gp0 = blockIdx.x * 32, kb0 = blockIdx.y * 32;
    const float* ksel = (kb0 < 256) ? k0 : k1;
    int j0 = kb0 & 255;
    float acc = 0.f;
    for (int c0 = 0; c0 < 256; c0 += 32) {
        int go = go_of_gp(gp0 + y);
        Wt[x][y] = w_ih[go * 256 + c0 + x];
        Ks[y][x] = ksel[(c0 + y) * 256 + j0 + x];
        __syncthreads();
#pragma unroll
        for (int cc = 0; cc < 32; cc++) acc += Wt[cc][x] * Ks[cc][y];
        __syncthreads();
    }
    d_AcatT[(kb0 + y) * NGO + gp0 + x] = acc;
}

__global__ void prep_W2(const float* __restrict__ w_ih,
                        const float* __restrict__ w_i2s) {
    __shared__ float Wt[32][33];
    __shared__ float Ms[32][33];
    int x = threadIdx.x, y = threadIdx.y;
    int gp0 = blockIdx.x * 32, ci0 = blockIdx.y * 32;
    float acc = 0.f;
    for (int c0 = 0; c0 < 256; c0 += 32) {
        int go = go_of_gp(gp0 + y);
        Wt[x][y] = w_ih[go * 256 + c0 + x];
        int ci = ci0 + x, c = c0 + y;
        float m = ((ci % 3) <= (c % 3)) ? 1.f : 0.f;
        Ms[y][x] = w_i2s[c * 256 + ci] * m;
        __syncthreads();
#pragma unroll
        for (int cc = 0; cc < 32; cc++) acc += Wt[cc][x] * Ms[cc][y];
        __syncthreads();
    }
    d_W2T[(ci0 + y) * NGO + gp0 + x] = acc;
}

__global__ void prep_bias(const float* __restrict__ w_ih,
                          const float* __restrict__ b_ih,
                          const float* __restrict__ b_hh,
                          const float* __restrict__ b_i2s,
                          const float* __restrict__ b_s2s) {
    int gp = threadIdx.x;
    int go = go_of_gp(gp);
    float s = b_ih[go] + b_hh[go];
    for (int c = 0; c < 256; c++)
        s += w_ih[go * 256 + c] * (b_i2s[c] + b_s2s[c]);
    d_biasT[gp] = s;
}

// ---------------- bf16 packing ----------------
__device__ __forceinline__ __nv_bfloat16 bf_hi(float f) { return __float2bfloat16(f); }
__device__ __forceinline__ __nv_bfloat16 bf_lo(float f) {
    __nv_bfloat16 h = __float2bfloat16(f);
    return __float2bfloat16(f - __bfloat162float(h));
}

__global__ void pack_W() {
    int i = blockIdx.x * blockDim.x + threadIdx.x;
    if (i >= NGO * KK_STEP) return;
    int gp = i / KK_STEP, kk = i % KK_STEP;
    int k = kk & 511;
    float f = d_AcatT[k * NGO + gp];
    d_Wb[i] = (kk < 1024) ? bf_hi(f) : bf_lo(f);
}

__global__ void pack_W2() {
    int i = blockIdx.x * blockDim.x + threadIdx.x;
    if (i >= NGO * KK_Y) return;
    int gp = i / KK_Y, kk = i % KK_Y;
    int k = kk & 255;
    float f = d_W2T[k * NGO + gp];
    d_W2b[i] = (kk < 512) ? bf_hi(f) : bf_lo(f);
}

__global__ void pack_X(const float* __restrict__ x) {
    __shared__ float tile[32][33];
    int tx = threadIdx.x, ty = threadIdx.y;
    int hw0 = blockIdx.x * 32, ci0 = blockIdx.y * 32, b = blockIdx.z;
    tile[ty][tx] = x[((size_t)(b * 256 + ci0 + ty)) * 4096 + hw0 + tx];
    __syncthreads();
    float v = tile[tx][ty];
    size_t row = (size_t)(b * 4096 + hw0 + ty);
    d_Xb[row * 512 + ci0 + tx] = bf_hi(v);
    d_Xb[row * 512 + 256 + ci0 + tx] = bf_lo(v);
}

__global__ void init_state() {
    int i = blockIdx.x * blockDim.x + threadIdx.x;
    if (i < MROWS * NC) {
        d_Hhi[0][i] = __float2bfloat16(0.f);
        d_Hlo[0][i] = __float2bfloat16(0.f);
        d_Cst[i] = 0.f;
    }
}

// ---------------- shared GEMM machinery ----------------
// smem: A stage s at s*STAGE_H halves; B stage s at 2*STAGE_H + s*STAGE_H
__device__ __forceinline__ void compute_chunk(uint32_t sA, uint32_t sB,
                                              int warp_m, int warp_n, int lane,
                                              float acc[4][4][4]) {
    int rsel = lane & 15, hsel = lane >> 4;         // A lane addressing
    int bn = (lane & 7), bh = (lane >> 3) & 1, btile = lane >> 4;  // B lane addressing
#pragma unroll
    for (int kc = 0; kc < 4; kc++) {
        uint32_t bfr[2][4];
#pragma unroll
        for (int p = 0; p < 2; p++) {
            uint32_t addr = sB + ((warp_n * 32 + p * 16 + btile * 8 + bn) * LDS_H
                                  + kc * 16 + bh * 8) * 2;
            ldm_x4(bfr[p], addr);
        }
#pragma unroll
        for (int mt = 0; mt < 4; mt++) {
            uint32_t af[4];
            uint32_t addr = sA + ((warp_m * 64 + mt * 16 + rsel) * LDS_H
                                  + kc * 16 + hsel * 8) * 2;
            ldm_x4(af, addr);
#pragma unroll
            for (int nt = 0; nt < 4; nt++)
                mma16816(acc[mt][nt], af, &bfr[nt >> 1][(nt & 1) * 2]);
        }
    }
}

// ---------------- step kernel: gates GEMM (mma.sync) + fused LSTM cell ----------------
__global__ void __launch_bounds__(256, 1) step_mma(int t) {
    uint32_t sbase = smem_u32(smem);
    int tid = threadIdx.x;
    int lane = tid & 31, wid = tid >> 5;
    int warp_m = wid & 1, warp_n = wid >> 1;
    int n0 = blockIdx.x * 128;   // gate-col base
    int r0 = blockIdx.y * 128;   // row base
    const __nv_bfloat16* Hhi = d_Hhi[t & 1];
    const __nv_bfloat16* Hlo = d_Hlo[t & 1];
    __nv_bfloat16* HhiO = d_Hhi[(t + 1) & 1];
    __nv_bfloat16* HloO = d_Hlo[(t + 1) & 1];

    float acc[4][4][4] = {};

    // issue one k64 chunk of A+B into stage (c&1)
    auto issue = [&](int c) {
        int buf = c & 1;
        int kk0 = c * 64;
        int seg = kk0 >> 9;            // 0:hi 1:lo 2:hi
        int ks = kk0 & 511;
        bool shifted = ks >= 256;      // Hcat second half -> row r+1
        int kb = ks & 255;
        const __nv_bfloat16* src = (seg == 1) ? Hlo : Hhi;
        uint32_t aoff = sbase + buf * STAGE_H * 2;
        uint32_t boff = sbase + (2 + buf) * STAGE_H * 2;
#pragma unroll
        for (int it = 0; it < 4; it++) {
            int u = it * 256 + tid;
            int row = u >> 3, k8 = u & 7;
            int rg = r0 + row;
            bool pred = !shifted || ((rg & 1023) != 1023);
            int rs = shifted ? min(rg + 1, MROWS - 1) : rg;
            const __nv_bfloat16* g = &src[(size_t)rs * NC + kb + k8 * 8];
            cp16(aoff + (row * LDS_H + k8 * 8) * 2, g, pred);
        }
#pragma unroll
        for (int it = 0; it < 4; it++) {
            int u = it * 256 + tid;
            int row = u >> 3, k8 = u & 7;
            const __nv_bfloat16* g = &d_Wb[(size_t)(n0 + row) * KK_STEP + kk0 + k8 * 8];
            cp16(boff + (row * LDS_H + k8 * 8) * 2, g, true);
        }
        cp_commit();
    };

    issue(0);
    for (int c = 0; c < NCH_STEP; c++) {
        if (c + 1 < NCH_STEP) { issue(c + 1); cp_wait<1>(); }
        else                  { cp_wait<0>(); }
        __syncthreads();
        int buf = c & 1;
        compute_chunk(sbase + buf * STAGE_H * 2, sbase + (2 + buf) * STAGE_H * 2,
                      warp_m, warp_n, lane, acc);
        __syncthreads();
    }

    // ---- epilogue: pair-exchange then fused LSTM cell ----
    // C fragment: c0,c1 -> row g, cols t*2,t*2+1 ; c2,c3 -> row g+8.
    // After xor-1 exchange: even lane owns row g (all 4 gates of its channel),
    // odd lane owns row g+8.
    int g4 = lane >> 2;
    bool oddl = (lane & 1);
    int rbase = r0 + warp_m * 64 + g4 + (oddl ? 8 : 0);
    int cobase = (n0 >> 2) + warp_n * 8 + ((lane >> 1) & 1);
#pragma unroll
    for (int mt = 0; mt < 4; mt++) {
        int r = rbase + mt * 16;
        int dir = r >> 10, bhv = r & 1023, bb = bhv >> 6, hh = bhv & 63;
        int dg = t - hh;
        bool has_y = (dg >= 0 && dg < 64);
        size_t ybase = 0;
        if (has_y) {
            int ww = dir ? (63 - dg) : dg;
            ybase = (size_t)((bb * 64 + hh) * 64 + ww) * NGO;
        }
#pragma unroll
        for (int nt = 0; nt < 4; nt++) {
            float* a = acc[mt][nt];
            // even lane sends its row-g+8 i,f (a2,a3); odd lane sends its row-g g,o (a0,a1)
            float s0 = __shfl_xor_sync(0xffffffffu, oddl ? a[0] : a[2], 1);
            float s1 = __shfl_xor_sync(0xffffffffu, oddl ? a[1] : a[3], 1);
            float gi, gf, gg, go;
            if (!oddl) { gi = a[0]; gf = a[1]; gg = s0;   go = s1;   }  // row g
            else       { gi = s0;   gf = s1;   gg = a[2]; go = a[3]; }  // row g+8 (FIX: was a[0],a[1])
            int co = cobase + nt * 2;
            float4 bv = *(const float4*)&d_biasT[co * 4];
            gi += bv.x; gf += bv.y; gg += bv.z; go += bv.w;
            if (has_y) {
                float4 yv = *(const float4*)&d_Y[ybase + co * 4];
                gi += yv.x; gf += yv.y; gg += yv.z; go += yv.w;
            }
            float si = fast_sig(gi), sf = fast_sig(gf), so = fast_sig(go);
            float cn = sf * d_Cst[r * NC + co] + si * fast_tanh(gg);
            float hv = so * fast_tanh(cn);
            d_Cst[r * NC + co] = cn;
            d_hs[((size_t)t * MROWS + r) * NC + co] = hv;
            __nv_bfloat16 hb = __float2bfloat16(hv);
            HhiO[r * NC + co] = hb;
            HloO[r * NC + co] = __float2bfloat16(hv - __bfloat162float(hb));
        }
    }
}

// ---------------- ygemm: d_Y = Xsplit @ W2split (mma.sync) ----------------
__global__ void __launch_bounds__(256, 1) ygemm_mma() {
    uint32_t sbase = smem_u32(smem);
    int tid = threadIdx.x;
    int lane = tid & 31, wid = tid >> 5;
    int warp_m = wid & 1, warp_n = wid >> 1;
    int n0 = blockIdx.x * 128;
    int r0 = blockIdx.y * 128;

    float acc[4][4][4] = {};

    auto issue = [&](int c) {
        int buf = c & 1;
        int kk0 = c * 64;
        int colbase = (kk0 < 512) ? kk0 : (kk0 - 512);
        uint32_t aoff = sbase + buf * STAGE_H * 2;
        uint32_t boff = sbase + (2 + buf) * STAGE_H * 2;
#pragma unroll
        for (int it = 0; it < 4; it++) {
            int u = it * 256 + tid;
            int row = u >> 3, k8 = u & 7;
            const __nv_bfloat16* g = &d_Xb[(size_t)(r0 + row) * 512 + colbase + k8 * 8];
            cp16(aoff + (row * LDS_H + k8 * 8) * 2, g, true);
        }
#pragma unroll
        for (int it = 0; it < 4; it++) {
            int u = it * 256 + tid;
            int row = u >> 3, k8 = u & 7;
            const __nv_bfloat16* g = &d_W2b[(size_t)(n0 + row) * KK_Y + kk0 + k8 * 8];
            cp16(boff + (row * LDS_H + k8 * 8) * 2, g, true);
        }
        cp_commit();
    };

    issue(0);
    for (int c = 0; c < NCH_Y; c++) {
        if (c + 1 < NCH_Y) { issue(c + 1); cp_wait<1>(); }
        else               { cp_wait<0>(); }
        __syncthreads();
        int buf = c & 1;
        compute_chunk(sbase + buf * STAGE_H * 2, sbase + (2 + buf) * STAGE_H * 2,
                      warp_m, warp_n, lane, acc);
        __syncthreads();
    }

    // epilogue: store raw gates (float2 per row-half)
    int g4 = lane >> 2;
    int col = n0 + warp_n * 32 + 2 * (lane & 3);
    int rA0 = r0 + warp_m * 64 + g4;
#pragma unroll
    for (int mt = 0; mt < 4; mt++) {
#pragma unroll
        for (int nt = 0; nt < 4; nt++) {
            float* a = acc[mt][nt];
            int cc = col + nt * 8;
            size_t pA = (size_t)(rA0 + mt * 16) * NGO + cc;
            size_t pB = (size_t)(rA0 + mt * 16 + 8) * NGO + cc;
            *(float2*)&d_Y[pA] = make_float2(a[0], a[1]);
            *(float2*)&d_Y[pB] = make_float2(a[2], a[3]);
        }
    }
}

// ---------------- output assembly (unchanged, validated) ----------------
__global__ void __launch_bounds__(256) output_kernel(float* __restrict__ out) {
    __shared__ float tile[127 * 65];
    int c2 = blockIdx.x, b = blockIdx.y;
    int tid = threadIdx.x;
    int hi = c2 >> 2;
    int coL = (c2 & 3) * 64;
    int rL = b * 64 + hi;
    for (int e = tid; e < 127 * 64; e += 256) {
        int tt = e >> 6, j = e & 63;
        tile[tt * 65 + j] = d_hs[((size_t)tt * MROWS + rL) * NC + coL + j];
    }
    __syncthreads();
    float rl[16];
#pragma unroll
    for (int it = 0; it < 16; it++) {
        int o = it * 256 + tid;
        int h2 = o >> 6, ww = o & 63;
        rl[it] = tile[(h2 + ww) * 65 + h2];
    }
    __syncthreads();
    int rR = 1024 + b * 64 + hi;
    for (int e = tid; e < 127 * 64; e += 256) {
        int tt = e >> 6, j = e & 63;
        tile[tt * 65 + j] = d_hs[((size_t)tt * MROWS + rR) * NC + coL + j];
    }
    __syncthreads();
    float* ob = out + ((size_t)(b * 256 + c2)) * 64 * 64;
#pragma unroll
    for (int it = 0; it < 16; it++) {
        int o = it * 256 + tid;
        int h2 = o >> 6, ww = o & 63;
        float rv = (h2 > 0) ? tile[(h2 + 62 - ww) * 65 + (h2 - 1)] : 0.f;
        ob[o] = rl[it] + rv;
    }
}

// ---------------- launch ----------------
extern "C" void kernel_launch(void* const* d_in, const int* in_sizes, int n_in,
                              void* d_out, int out_size) {
    const float* x     = (const float*)d_in[0];
    const float* w_i2s = (const float*)d_in[1];
    const float* b_i2s = (const float*)d_in[2];
    const float* w_ih  = (const float*)d_in[3];
    const float* b_ih  = (const float*)d_in[4];
    const float* b_hh  = (const float*)d_in[5];
    const float* k0    = (const float*)d_in[6];
    const float* k1    = (const float*)d_in[7];
    const float* b_s2s = (const float*)d_in[8];
    float* out = (float*)d_out;

    cudaFuncSetAttribute(step_mma,  cudaFuncAttributeMaxDynamicSharedMemorySize, SMEM_BYTES);
    cudaFuncSetAttribute(ygemm_mma, cudaFuncAttributeMaxDynamicSharedMemorySize, SMEM_BYTES);

    prep_A  <<<dim3(32, 16), dim3(32, 32)>>>(w_ih, k0, k1);
    prep_W2 <<<dim3(32, 8),  dim3(32, 32)>>>(w_ih, w_i2s);
    prep_bias<<<1, 1024>>>(w_ih, b_ih, b_hh, b_i2s, b_s2s);
    pack_W  <<<(NGO * KK_STEP + 255) / 256, 256>>>();
    pack_W2 <<<(NGO * KK_Y + 255) / 256, 256>>>();
    pack_X  <<<dim3(128, 8, 16), dim3(32, 32)>>>(x);
    init_state<<<(MROWS * NC + 255) / 256, 256>>>();

    ygemm_mma<<<dim3(8, 512), 256, SMEM_BYTES>>>();

    for (int t = 0; t < WD; t++)
        step_mma<<<dim3(8, 16), 256, SMEM_BYTES>>>(t);

    output_kernel<<<dim3(256, 16), 256>>>(out);
}

// round 7
// speedup vs baseline: 3.5096x; 2.3776x over previous
#include <cuda_runtime.h>
#include <cuda_fp16.h>
#include <math.h>
#include <stdint.h>

// ---------------- problem constants ----------------
#define WD    127
#define NB    16
#define NH    64
#define NW    64
#define NC    256
#define MROWS 2048
#define NGO   1024
#define YROWS 65536        // NB*NH*NW
#define KK_STEP 512        // fp16 single-term
#define KK_Y    256
#define NCH_STEP 8         // KK_STEP / 64
#define NCH_Y    4
#define LDS_H   72         // smem row stride in halves (144B, conflict-free ldmatrix)
#define STAGE_H (128 * LDS_H)
#define NSTAGE  3
#define SMEM_BYTES (2 * NSTAGE * STAGE_H * 2)   // A+B x 3 stages = 110592 B

// ---------------- persistent device scratch ----------------
__device__ __align__(128) float d_Y[(size_t)YROWS * NGO];
__device__ __align__(128) float d_hs[(size_t)WD * MROWS * NC];
__device__ __align__(128) float d_Cst[MROWS * NC];
__device__ __align__(128) __half d_H[2][MROWS * NC];
__device__ __align__(128) float d_AcatT[512 * NGO];
__device__ __align__(128) float d_W2T[256 * NGO];
__device__ __align__(128) float d_biasT[NGO];
__device__ __align__(128) __half d_Wh[NGO * KK_STEP];    // [gp][k]
__device__ __align__(128) __half d_W2h[NGO * KK_Y];      // [gp][k]
__device__ __align__(128) __half d_Xh[(size_t)YROWS * KK_Y]; // [r][ci]

__device__ __forceinline__ int go_of_gp(int gp) { return (gp & 3) * 256 + (gp >> 2); }

// ---------------- baseline-PTX helpers (compile under compute_103) ----------------
__device__ __forceinline__ uint32_t smem_u32(const void* p) {
    uint32_t a;
    asm("{ .reg .u64 t; cvta.to.shared.u64 t, %1; cvt.u32.u64 %0, t; }" : "=r"(a) : "l"(p));
    return a;
}
__device__ __forceinline__ void cp16(uint32_t dst, const void* src, bool pred) {
    int sz = pred ? 16 : 0;   // src-size 0 -> 16B zero-fill
    asm volatile("cp.async.cg.shared.global [%0], [%1], 16, %2;"
                 :: "r"(dst), "l"(src), "r"(sz) : "memory");
}
__device__ __forceinline__ void cp_commit() { asm volatile("cp.async.commit_group;" ::: "memory"); }
template <int N>
__device__ __forceinline__ void cp_wait() { asm volatile("cp.async.wait_group %0;" :: "n"(N) : "memory"); }

__device__ __forceinline__ void ldm_x4(uint32_t* r, uint32_t addr) {
    asm volatile("ldmatrix.sync.aligned.m8n8.x4.shared.b16 {%0,%1,%2,%3}, [%4];"
                 : "=r"(r[0]), "=r"(r[1]), "=r"(r[2]), "=r"(r[3]) : "r"(addr));
}
__device__ __forceinline__ void mma16816(float* c, const uint32_t* a, const uint32_t* b) {
    asm volatile("mma.sync.aligned.m16n8k16.row.col.f32.f16.f16.f32 "
                 "{%0,%1,%2,%3}, {%4,%5,%6,%7}, {%8,%9}, {%0,%1,%2,%3};"
                 : "+f"(c[0]), "+f"(c[1]), "+f"(c[2]), "+f"(c[3])
                 : "r"(a[0]), "r"(a[1]), "r"(a[2]), "r"(a[3]), "r"(b[0]), "r"(b[1]));
}
__device__ __forceinline__ float fast_tanh(float x) {
    x = fminf(fmaxf(x, -15.f), 15.f);
    float e = __expf(2.f * x);
    return (e - 1.f) / (e + 1.f);
}
__device__ __forceinline__ float fast_sig(float x) { return 1.f / (1.f + __expf(-x)); }

extern __shared__ __align__(1024) __half smem[];

// ---------------- prep kernels (fp32 weight fusion) ----------------
__global__ void prep_A(const float* __restrict__ w_ih,
                       const float* __restrict__ k0,
                       const float* __restrict__ k1) {
    __shared__ float Wt[32][33];
    __shared__ float Ks[32][33];
    int x = threadIdx.x, y = threadIdx.y;
    int gp0 = blockIdx.x * 32, kb0 = blockIdx.y * 32;
    const float* ksel = (kb0 < 256) ? k0 : k1;
    int j0 = kb0 & 255;
    float acc = 0.f;
    for (int c0 = 0; c0 < 256; c0 += 32) {
        int go = go_of_gp(gp0 + y);
        Wt[x][y] = w_ih[go * 256 + c0 + x];
        Ks[y][x] = ksel[(c0 + y) * 256 + j0 + x];
        __syncthreads();
#pragma unroll
        for (int cc = 0; cc < 32; cc++) acc += Wt[cc][x] * Ks[cc][y];
        __syncthreads();
    }
    d_AcatT[(kb0 + y) * NGO + gp0 + x] = acc;
}

__global__ void prep_W2(const float* __restrict__ w_ih,
                        const float* __restrict__ w_i2s) {
    __shared__ float Wt[32][33];
    __shared__ float Ms[32][33];
    int x = threadIdx.x, y = threadIdx.y;
    int gp0 = blockIdx.x * 32, ci0 = blockIdx.y * 32;
    float acc = 0.f;
    for (int c0 = 0; c0 < 256; c0 += 32) {
        int go = go_of_gp(gp0 + y);
        Wt[x][y] = w_ih[go * 256 + c0 + x];
        int ci = ci0 + x, c = c0 + y;
        float m = ((ci % 3) <= (c % 3)) ? 1.f : 0.f;
        Ms[y][x] = w_i2s[c * 256 + ci] * m;
        __syncthreads();
#pragma unroll
        for (int cc = 0; cc < 32; cc++) acc += Wt[cc][x] * Ms[cc][y];
        __syncthreads();
    }
    d_W2T[(ci0 + y) * NGO + gp0 + x] = acc;
}

__global__ void prep_bias(const float* __restrict__ w_ih,
                          const float* __restrict__ b_ih,
                          const float* __restrict__ b_hh,
                          const float* __restrict__ b_i2s,
                          const float* __restrict__ b_s2s) {
    int gp = threadIdx.x;
    int go = go_of_gp(gp);
    float s = b_ih[go] + b_hh[go];
    for (int c = 0; c < 256; c++)
        s += w_ih[go * 256 + c] * (b_i2s[c] + b_s2s[c]);
    d_biasT[gp] = s;
}

// ---------------- fp16 packing ----------------
__global__ void pack_W() {
    int i = blockIdx.x * blockDim.x + threadIdx.x;
    if (i >= NGO * KK_STEP) return;
    int gp = i / KK_STEP, k = i % KK_STEP;
    d_Wh[i] = __float2half(d_AcatT[k * NGO + gp]);
}

__global__ void pack_W2() {
    int i = blockIdx.x * blockDim.x + threadIdx.x;
    if (i >= NGO * KK_Y) return;
    int gp = i / KK_Y, k = i % KK_Y;
    d_W2h[i] = __float2half(d_W2T[k * NGO + gp]);
}

__global__ void pack_X(const float* __restrict__ x) {
    __shared__ float tile[32][33];
    int tx = threadIdx.x, ty = threadIdx.y;
    int hw0 = blockIdx.x * 32, ci0 = blockIdx.y * 32, b = blockIdx.z;
    tile[ty][tx] = x[((size_t)(b * 256 + ci0 + ty)) * 4096 + hw0 + tx];
    __syncthreads();
    float v = tile[tx][ty];
    size_t row = (size_t)(b * 4096 + hw0 + ty);
    d_Xh[row * KK_Y + ci0 + tx] = __float2half(v);
}

__global__ void init_state() {
    int i = blockIdx.x * blockDim.x + threadIdx.x;
    if (i < MROWS * NC) {
        d_H[0][i] = __float2half(0.f);
        d_Cst[i] = 0.f;
    }
}

// ---------------- shared GEMM machinery ----------------
// smem: A stage s at s*STAGE_H halves; B stage s at (NSTAGE+s)*STAGE_H
__device__ __forceinline__ void compute_chunk(uint32_t sA, uint32_t sB,
                                              int warp_m, int warp_n, int lane,
                                              float acc[4][4][4]) {
    int rsel = lane & 15, hsel = lane >> 4;
    int bn = (lane & 7), bh = (lane >> 3) & 1, btile = lane >> 4;
#pragma unroll
    for (int kc = 0; kc < 4; kc++) {
        uint32_t bfr[2][4];
#pragma unroll
        for (int p = 0; p < 2; p++) {
            uint32_t addr = sB + ((warp_n * 32 + p * 16 + btile * 8 + bn) * LDS_H
                                  + kc * 16 + bh * 8) * 2;
            ldm_x4(bfr[p], addr);
        }
#pragma unroll
        for (int mt = 0; mt < 4; mt++) {
            uint32_t af[4];
            uint32_t addr = sA + ((warp_m * 64 + mt * 16 + rsel) * LDS_H
                                  + kc * 16 + hsel * 8) * 2;
            ldm_x4(af, addr);
#pragma unroll
            for (int nt = 0; nt < 4; nt++)
                mma16816(acc[mt][nt], af, &bfr[nt >> 1][(nt & 1) * 2]);
        }
    }
}

// ---------------- step kernel: gates GEMM (fp16 mma) + fused LSTM cell ----------------
__global__ void __launch_bounds__(256, 1) step_mma(int t) {
    uint32_t sbase = smem_u32(smem);
    int tid = threadIdx.x;
    int lane = tid & 31, wid = tid >> 5;
    int warp_m = wid & 1, warp_n = wid >> 1;
    int n0 = blockIdx.x * 128;   // gate-col base
    int r0 = blockIdx.y * 128;   // row base
    const __half* Hin = d_H[t & 1];
    __half* HO = d_H[(t + 1) & 1];

    float acc[4][4][4] = {};

    auto issue = [&](int c) {
        int buf = c % NSTAGE;
        int kk0 = c * 64;
        bool shifted = kk0 >= 256;     // Hcat second half -> row r+1
        int kb = kk0 & 255;
        uint32_t aoff = sbase + buf * STAGE_H * 2;
        uint32_t boff = sbase + (NSTAGE + buf) * STAGE_H * 2;
#pragma unroll
        for (int it = 0; it < 4; it++) {
            int u = it * 256 + tid;
            int row = u >> 3, k8 = u & 7;
            int rg = r0 + row;
            bool pred = !shifted || ((rg & 1023) != 1023);
            int rs = shifted ? min(rg + 1, MROWS - 1) : rg;
            cp16(aoff + (row * LDS_H + k8 * 8) * 2,
                 &Hin[(size_t)rs * NC + kb + k8 * 8], pred);
        }
#pragma unroll
        for (int it = 0; it < 4; it++) {
            int u = it * 256 + tid;
            int row = u >> 3, k8 = u & 7;
            cp16(boff + (row * LDS_H + k8 * 8) * 2,
                 &d_Wh[(size_t)(n0 + row) * KK_STEP + kk0 + k8 * 8], true);
        }
        cp_commit();
    };

    issue(0);
    issue(1);
#pragma unroll
    for (int c = 0; c < NCH_STEP; c++) {
        if (c + 1 < NCH_STEP) cp_wait<1>();
        else                  cp_wait<0>();
        __syncthreads();
        if (c + 2 < NCH_STEP) issue(c + 2);
        int buf = c % NSTAGE;
        compute_chunk(sbase + buf * STAGE_H * 2,
                      sbase + (NSTAGE + buf) * STAGE_H * 2,
                      warp_m, warp_n, lane, acc);
    }

    // ---- epilogue: pair-exchange then fused LSTM cell ----
    // C fragment: c0,c1 -> row g cols t2,t2+1 ; c2,c3 -> row g+8.
    int g4 = lane >> 2;
    bool oddl = (lane & 1);
    int rbase = r0 + warp_m * 64 + g4 + (oddl ? 8 : 0);
    int cobase = (n0 >> 2) + warp_n * 8 + ((lane >> 1) & 1);
#pragma unroll
    for (int mt = 0; mt < 4; mt++) {
        int r = rbase + mt * 16;
        int dir = r >> 10, bhv = r & 1023, bb = bhv >> 6, hh = bhv & 63;
        int dg = t - hh;
        bool has_y = (dg >= 0 && dg < 64);
        size_t ybase = 0;
        if (has_y) {
            int ww = dir ? (63 - dg) : dg;
            ybase = (size_t)((bb * 64 + hh) * 64 + ww) * NGO;
        }
#pragma unroll
        for (int nt = 0; nt < 4; nt++) {
            float* a = acc[mt][nt];
            float s0 = __shfl_xor_sync(0xffffffffu, oddl ? a[0] : a[2], 1);
            float s1 = __shfl_xor_sync(0xffffffffu, oddl ? a[1] : a[3], 1);
            float gi, gf, gg, go;
            if (!oddl) { gi = a[0]; gf = a[1]; gg = s0;   go = s1;   }  // row g
            else       { gi = s0;   gf = s1;   gg = a[2]; go = a[3]; }  // row g+8
            int co = cobase + nt * 2;
            float4 bv = *(const float4*)&d_biasT[co * 4];
            gi += bv.x; gf += bv.y; gg += bv.z; go += bv.w;
            if (has_y) {
                float4 yv = *(const float4*)&d_Y[ybase + co * 4];
                gi += yv.x; gf += yv.y; gg += yv.z; go += yv.w;
            }
            float si = fast_sig(gi), sf = fast_sig(gf), so = fast_sig(go);
            float cn = sf * d_Cst[r * NC + co] + si * fast_tanh(gg);
            float hv = so * fast_tanh(cn);
            d_Cst[r * NC + co] = cn;
            d_hs[((size_t)t * MROWS + r) * NC + co] = hv;
            HO[r * NC + co] = __float2half(hv);
        }
    }
}

// ---------------- ygemm: d_Y = X @ W2 (fp16 mma) ----------------
__global__ void __launch_bounds__(256, 1) ygemm_mma() {
    uint32_t sbase = smem_u32(smem);
    int tid = threadIdx.x;
    int lane = tid & 31, wid = tid >> 5;
    int warp_m = wid & 1, warp_n = wid >> 1;
    int n0 = blockIdx.x * 128;
    int r0 = blockIdx.y * 128;

    float acc[4][4][4] = {};

    auto issue = [&](int c) {
        int buf = c % NSTAGE;
        int kk0 = c * 64;
        uint32_t aoff = sbase + buf * STAGE_H * 2;
        uint32_t boff = sbase + (NSTAGE + buf) * STAGE_H * 2;
#pragma unroll
        for (int it = 0; it < 4; it++) {
            int u = it * 256 + tid;
            int row = u >> 3, k8 = u & 7;
            cp16(aoff + (row * LDS_H + k8 * 8) * 2,
                 &d_Xh[(size_t)(r0 + row) * KK_Y + kk0 + k8 * 8], true);
        }
#pragma unroll
        for (int it = 0; it < 4; it++) {
            int u = it * 256 + tid;
            int row = u >> 3, k8 = u & 7;
            cp16(boff + (row * LDS_H + k8 * 8) * 2,
                 &d_W2h[(size_t)(n0 + row) * KK_Y + kk0 + k8 * 8], true);
        }
        cp_commit();
    };

    issue(0);
    issue(1);
#pragma unroll
    for (int c = 0; c < NCH_Y; c++) {
        if (c + 1 < NCH_Y) cp_wait<1>();
        else               cp_wait<0>();
        __syncthreads();
        if (c + 2 < NCH_Y) issue(c + 2);
        int buf = c % NSTAGE;
        compute_chunk(sbase + buf * STAGE_H * 2,
                      sbase + (NSTAGE + buf) * STAGE_H * 2,
                      warp_m, warp_n, lane, acc);
    }

    // epilogue: store raw gates
    int g4 = lane >> 2;
    int col = n0 + warp_n * 32 + 2 * (lane & 3);
    int rA0 = r0 + warp_m * 64 + g4;
#pragma unroll
    for (int mt = 0; mt < 4; mt++) {
#pragma unroll
        for (int nt = 0; nt < 4; nt++) {
            float* a = acc[mt][nt];
            int cc = col + nt * 8;
            size_t pA = (size_t)(rA0 + mt * 16) * NGO + cc;
            size_t pB = (size_t)(rA0 + mt * 16 + 8) * NGO + cc;
            *(float2*)&d_Y[pA] = make_float2(a[0], a[1]);
            *(float2*)&d_Y[pB] = make_float2(a[2], a[3]);
        }
    }
}

// ---------------- output assembly (validated) ----------------
__global__ void __launch_bounds__(256) output_kernel(float* __restrict__ out) {
    __shared__ float tile[127 * 65];
    int c2 = blockIdx.x, b = blockIdx.y;
    int tid = threadIdx.x;
    int hi = c2 >> 2;
    int coL = (c2 & 3) * 64;
    int rL = b * 64 + hi;
    for (int e = tid; e < 127 * 64; e += 256) {
        int tt = e >> 6, j = e & 63;
        tile[tt * 65 + j] = d_hs[((size_t)tt * MROWS + rL) * NC + coL + j];
    }
    __syncthreads();
    float rl[16];
#pragma unroll
    for (int it = 0; it < 16; it++) {
        int o = it * 256 + tid;
        int h2 = o >> 6, ww = o & 63;
        rl[it] = tile[(h2 + ww) * 65 + h2];
    }
    __syncthreads();
    int rR = 1024 + b * 64 + hi;
    for (int e = tid; e < 127 * 64; e += 256) {
        int tt = e >> 6, j = e & 63;
        tile[tt * 65 + j] = d_hs[((size_t)tt * MROWS + rR) * NC + coL + j];
    }
    __syncthreads();
    float* ob = out + ((size_t)(b * 256 + c2)) * 64 * 64;
#pragma unroll
    for (int it = 0; it < 16; it++) {
        int o = it * 256 + tid;
        int h2 = o >> 6, ww = o & 63;
        float rv = (h2 > 0) ? tile[(h2 + 62 - ww) * 65 + (h2 - 1)] : 0.f;
        ob[o] = rl[it] + rv;
    }
}

// ---------------- launch ----------------
extern "C" void kernel_launch(void* const* d_in, const int* in_sizes, int n_in,
                              void* d_out, int out_size) {
    const float* x     = (const float*)d_in[0];
    const float* w_i2s = (const float*)d_in[1];
    const float* b_i2s = (const float*)d_in[2];
    const float* w_ih  = (const float*)d_in[3];
    const float* b_ih  = (const float*)d_in[4];
    const float* b_hh  = (const float*)d_in[5];
    const float* k0    = (const float*)d_in[6];
    const float* k1    = (const float*)d_in[7];
    const float* b_s2s = (const float*)d_in[8];
    float* out = (float*)d_out;

    cudaFuncSetAttribute(step_mma,  cudaFuncAttributeMaxDynamicSharedMemorySize, SMEM_BYTES);
    cudaFuncSetAttribute(ygemm_mma, cudaFuncAttributeMaxDynamicSharedMemorySize, SMEM_BYTES);

    prep_A  <<<dim3(32, 16), dim3(32, 32)>>>(w_ih, k0, k1);
    prep_W2 <<<dim3(32, 8),  dim3(32, 32)>>>(w_ih, w_i2s);
    prep_bias<<<1, 1024>>>(w_ih, b_ih, b_hh, b_i2s, b_s2s);
    pack_W  <<<(NGO * KK_STEP + 255) / 256, 256>>>();
    pack_W2 <<<(NGO * KK_Y + 255) / 256, 256>>>();
    pack_X  <<<dim3(128, 8, 16), dim3(32, 32)>>>(x);
    init_state<<<(MROWS * NC + 255) / 256, 256>>>();

    ygemm_mma<<<dim3(8, 512), 256, SMEM_BYTES>>>();

    for (int t = 0; t < WD; t++)
        step_mma<<<dim3(8, 16), 256, SMEM_BYTES>>>(t);

    output_kernel<<<dim3(256, 16), 256>>>(out);
}

// round 8
// speedup vs baseline: 5.4439x; 1.5511x over previous
#include <cuda_runtime.h>
#include <cuda_fp16.h>
#include <math.h>
#include <stdint.h>

// ---------------- problem constants ----------------
#define WD    127
#define NB    16
#define NH    64
#define NW    64
#define NC    256
#define MROWS 2048
#define NGO   1024
#define YROWS 65536        // NB*NH*NW
#define KK_STEP 512        // fp16 single-term
#define KK_Y    256
#define NCH_STEP 8         // KK_STEP / 64
#define NCH_Y    4
#define LDS_H   72         // A smem row stride in halves (144B, conflict-free ldmatrix)
#define A_STAGE_H (128 * LDS_H)          // 9216 halves per A stage
#define NSTAGE  3

// persistent step kernel smem: 3 A stages + resident B slice
#define BLDS    520                      // B row stride in halves (1040B)
#define SM_B_H  (NSTAGE * A_STAGE_H)     // B starts at 27648 halves
#define SMEM_STEP ((SM_B_H + 128 * BLDS) * 2)   // 188416 bytes

// ygemm smem: 3 A stages + 3 B stages (per-chunk tiles)
#define SMEM_Y  (2 * NSTAGE * A_STAGE_H * 2)    // 110592 bytes

#define NBLK_STEP 128    // 8 x 16 grid, must be co-resident for sw barrier

// ---------------- persistent device scratch ----------------
__device__ __align__(128) float d_Y[(size_t)YROWS * NGO];
__device__ __align__(128) float d_hs[(size_t)WD * MROWS * NC];
__device__ __align__(128) __half d_H[2][MROWS * NC];
__device__ __align__(128) float d_AcatT[512 * NGO];
__device__ __align__(128) float d_W2T[256 * NGO];
__device__ __align__(128) float d_biasT[NGO];
__device__ __align__(128) __half d_Wh[NGO * KK_STEP];        // [gp][k]
__device__ __align__(128) __half d_W2h[NGO * KK_Y];          // [gp][k]
__device__ __align__(128) __half d_Xh[(size_t)YROWS * KK_Y]; // [r][ci]
__device__ unsigned g_bar_count = 0;
__device__ volatile unsigned g_bar_gen = 0;

__device__ __forceinline__ int go_of_gp(int gp) { return (gp & 3) * 256 + (gp >> 2); }

// ---------------- baseline-PTX helpers (compile under compute_103) ----------------
__device__ __forceinline__ uint32_t smem_u32(const void* p) {
    uint32_t a;
    asm("{ .reg .u64 t; cvta.to.shared.u64 t, %1; cvt.u32.u64 %0, t; }" : "=r"(a) : "l"(p));
    return a;
}
__device__ __forceinline__ void cp16(uint32_t dst, const void* src, bool pred) {
    int sz = pred ? 16 : 0;   // src-size 0 -> 16B zero-fill
    asm volatile("cp.async.cg.shared.global [%0], [%1], 16, %2;"
                 :: "r"(dst), "l"(src), "r"(sz) : "memory");
}
__device__ __forceinline__ void cp_commit() { asm volatile("cp.async.commit_group;" ::: "memory"); }
template <int N>
__device__ __forceinline__ void cp_wait() { asm volatile("cp.async.wait_group %0;" :: "n"(N) : "memory"); }

__device__ __forceinline__ void ldm_x4(uint32_t* r, uint32_t addr) {
    asm volatile("ldmatrix.sync.aligned.m8n8.x4.shared.b16 {%0,%1,%2,%3}, [%4];"
                 : "=r"(r[0]), "=r"(r[1]), "=r"(r[2]), "=r"(r[3]) : "r"(addr));
}
__device__ __forceinline__ void mma16816(float* c, const uint32_t* a, const uint32_t* b) {
    asm volatile("mma.sync.aligned.m16n8k16.row.col.f32.f16.f16.f32 "
                 "{%0,%1,%2,%3}, {%4,%5,%6,%7}, {%8,%9}, {%0,%1,%2,%3};"
                 : "+f"(c[0]), "+f"(c[1]), "+f"(c[2]), "+f"(c[3])
                 : "r"(a[0]), "r"(a[1]), "r"(a[2]), "r"(a[3]), "r"(b[0]), "r"(b[1]));
}
__device__ __forceinline__ float fast_tanh(float x) {
    x = fminf(fmaxf(x, -15.f), 15.f);
    float e = __expf(2.f * x);
    return (e - 1.f) / (e + 1.f);
}
__device__ __forceinline__ float fast_sig(float x) { return 1.f / (1.f + __expf(-x)); }

// software grid barrier (all NBLK_STEP CTAs co-resident: 188KB smem -> 1 CTA/SM, 128 <= 148 SMs)
__device__ __forceinline__ void grid_sync_sw() {
    __syncthreads();
    if (threadIdx.x == 0) {
        __threadfence();                       // release: make this CTA's writes visible
        unsigned gen = g_bar_gen;
        if (atomicInc(&g_bar_count, NBLK_STEP - 1) == NBLK_STEP - 1) {
            g_bar_gen = gen + 1;               // last arrival releases everyone
        } else {
            while (g_bar_gen == gen) __nanosleep(64);
        }
        __threadfence();                       // acquire
    }
    __syncthreads();
}

extern __shared__ __align__(1024) __half smem[];

// ---------------- prep kernels (fp32 weight fusion) ----------------
__global__ void prep_A(const float* __restrict__ w_ih,
                       const float* __restrict__ k0,
                       const float* __restrict__ k1) {
    __shared__ float Wt[32][33];
    __shared__ float Ks[32][33];
    int x = threadIdx.x, y = threadIdx.y;
    int gp0 = blockIdx.x * 32, kb0 = blockIdx.y * 32;
    const float* ksel = (kb0 < 256) ? k0 : k1;
    int j0 = kb0 & 255;
    float acc = 0.f;
    for (int c0 = 0; c0 < 256; c0 += 32) {
        int go = go_of_gp(gp0 + y);
        Wt[x][y] = w_ih[go * 256 + c0 + x];
        Ks[y][x] = ksel[(c0 + y) * 256 + j0 + x];
        __syncthreads();
#pragma unroll
        for (int cc = 0; cc < 32; cc++) acc += Wt[cc][x] * Ks[cc][y];
        __syncthreads();
    }
    d_AcatT[(kb0 + y) * NGO + gp0 + x] = acc;
}

__global__ void prep_W2(const float* __restrict__ w_ih,
                        const float* __restrict__ w_i2s) {
    __shared__ float Wt[32][33];
    __shared__ float Ms[32][33];
    int x = threadIdx.x, y = threadIdx.y;
    int gp0 = blockIdx.x * 32, ci0 = blockIdx.y * 32;
    float acc = 0.f;
    for (int c0 = 0; c0 < 256; c0 += 32) {
        int go = go_of_gp(gp0 + y);
        Wt[x][y] = w_ih[go * 256 + c0 + x];
        int ci = ci0 + x, c = c0 + y;
        float m = ((ci % 3) <= (c % 3)) ? 1.f : 0.f;
        Ms[y][x] = w_i2s[c * 256 + ci] * m;
        __syncthreads();
#pragma unroll
        for (int cc = 0; cc < 32; cc++) acc += Wt[cc][x] * Ms[cc][y];
        __syncthreads();
    }
    d_W2T[(ci0 + y) * NGO + gp0 + x] = acc;
}

__global__ void prep_bias(const float* __restrict__ w_ih,
                          const float* __restrict__ b_ih,
                          const float* __restrict__ b_hh,
                          const float* __restrict__ b_i2s,
                          const float* __restrict__ b_s2s) {
    int gp = threadIdx.x;
    int go = go_of_gp(gp);
    float s = b_ih[go] + b_hh[go];
    for (int c = 0; c < 256; c++)
        s += w_ih[go * 256 + c] * (b_i2s[c] + b_s2s[c]);
    d_biasT[gp] = s;
}

// ---------------- fp16 packing ----------------
__global__ void pack_W() {
    int i = blockIdx.x * blockDim.x + threadIdx.x;
    if (i >= NGO * KK_STEP) return;
    int gp = i / KK_STEP, k = i % KK_STEP;
    d_Wh[i] = __float2half(d_AcatT[k * NGO + gp]);
}

__global__ void pack_W2() {
    int i = blockIdx.x * blockDim.x + threadIdx.x;
    if (i >= NGO * KK_Y) return;
    int gp = i / KK_Y, k = i % KK_Y;
    d_W2h[i] = __float2half(d_W2T[k * NGO + gp]);
}

__global__ void pack_X(const float* __restrict__ x) {
    __shared__ float tile[32][33];
    int tx = threadIdx.x, ty = threadIdx.y;
    int hw0 = blockIdx.x * 32, ci0 = blockIdx.y * 32, b = blockIdx.z;
    tile[ty][tx] = x[((size_t)(b * 256 + ci0 + ty)) * 4096 + hw0 + tx];
    __syncthreads();
    float v = tile[tx][ty];
    size_t row = (size_t)(b * 4096 + hw0 + ty);
    d_Xh[row * KK_Y + ci0 + tx] = __float2half(v);
}

__global__ void init_state() {
    int i = blockIdx.x * blockDim.x + threadIdx.x;
    if (i < MROWS * NC) d_H[0][i] = __float2half(0.f);
    if (i == 0) { g_bar_count = 0; }   // defensive (barrier is self-balancing)
}

// ---------------- persistent step kernel ----------------
// Grid (8,16) x 256 thr. B weights resident in smem; C state in registers;
// one software grid barrier per diagonal step.
__global__ void __launch_bounds__(256, 1) step_persist() {
    uint32_t sbase = smem_u32(smem);
    int tid = threadIdx.x;
    int lane = tid & 31, wid = tid >> 5;
    int warp_m = wid & 1, warp_n = wid >> 1;
    int n0 = blockIdx.x * 128;   // gate-col base
    int r0 = blockIdx.y * 128;   // row base
    uint32_t sB = sbase + SM_B_H * 2;

    // ---- one-time B fill: 128 rows x 512 k halves ----
#pragma unroll
    for (int it = 0; it < 32; it++) {
        int u = it * 256 + tid;
        int row = u >> 6, k8 = u & 63;
        cp16(sB + (row * BLDS + k8 * 8) * 2,
             &d_Wh[(size_t)(n0 + row) * KK_STEP + k8 * 8], true);
    }
    cp_commit();
    cp_wait<0>();
    __syncthreads();

    // fixed epilogue mapping (step-invariant)
    int g4 = lane >> 2;
    bool oddl = (lane & 1);
    int rbase = r0 + warp_m * 64 + g4 + (oddl ? 8 : 0);
    int cobase = (n0 >> 2) + warp_n * 8 + ((lane >> 1) & 1);
    int rsel = lane & 15, hsel = lane >> 4;                        // A ldmatrix lanes
    int bn = (lane & 7), bh = (lane >> 3) & 1, btile = lane >> 4;  // B ldmatrix lanes

    float cst[4][4] = {};   // cell state lives in registers for the whole scan

    for (int t = 0; t < WD; t++) {
        const __half* Hin = d_H[t & 1];
        __half* HO = d_H[(t + 1) & 1];
        float acc[4][4][4] = {};

        auto issueA = [&](int c) {
            int buf = c % NSTAGE;
            int kk0 = c * 64;
            bool shifted = kk0 >= 256;     // Hcat second half -> row r+1
            int kb = kk0 & 255;
            uint32_t aoff = sbase + buf * A_STAGE_H * 2;
#pragma unroll
            for (int it = 0; it < 4; it++) {
                int u = it * 256 + tid;
                int row = u >> 3, k8 = u & 7;
                int rg = r0 + row;
                bool pred = !shifted || ((rg & 1023) != 1023);
                int rs = shifted ? min(rg + 1, MROWS - 1) : rg;
                cp16(aoff + (row * LDS_H + k8 * 8) * 2,
                     &Hin[(size_t)rs * NC + kb + k8 * 8], pred);
            }
            cp_commit();
        };

        issueA(0);
        issueA(1);
#pragma unroll
        for (int c = 0; c < NCH_STEP; c++) {
            if (c + 1 < NCH_STEP) cp_wait<1>();
            else                  cp_wait<0>();
            __syncthreads();
            if (c + 2 < NCH_STEP) issueA(c + 2);
            uint32_t sA = sbase + (c % NSTAGE) * A_STAGE_H * 2;
#pragma unroll
            for (int kc = 0; kc < 4; kc++) {
                int kabs = c * 64 + kc * 16 + bh * 8;
                uint32_t bfr[2][4];
#pragma unroll
                for (int p = 0; p < 2; p++) {
                    uint32_t addr = sB + ((warp_n * 32 + p * 16 + btile * 8 + bn) * BLDS
                                          + kabs) * 2;
                    ldm_x4(bfr[p], addr);
                }
#pragma unroll
                for (int mt = 0; mt < 4; mt++) {
                    uint32_t af[4];
                    uint32_t addr = sA + ((warp_m * 64 + mt * 16 + rsel) * LDS_H
                                          + kc * 16 + hsel * 8) * 2;
                    ldm_x4(af, addr);
#pragma unroll
                    for (int nt = 0; nt < 4; nt++)
                        mma16816(acc[mt][nt], af, &bfr[nt >> 1][(nt & 1) * 2]);
                }
            }
        }

        // ---- epilogue: pair-exchange + fused LSTM cell (C in registers) ----
#pragma unroll
        for (int mt = 0; mt < 4; mt++) {
            int r = rbase + mt * 16;
            int dir = r >> 10, bhv = r & 1023, bb = bhv >> 6, hh = bhv & 63;
            int dg = t - hh;
            bool has_y = (dg >= 0 && dg < 64);
            size_t ybase = 0;
            if (has_y) {
                int ww = dir ? (63 - dg) : dg;
                ybase = (size_t)((bb * 64 + hh) * 64 + ww) * NGO;
            }
#pragma unroll
            for (int nt = 0; nt < 4; nt++) {
                float* a = acc[mt][nt];
                float s0 = __shfl_xor_sync(0xffffffffu, oddl ? a[0] : a[2], 1);
                float s1 = __shfl_xor_sync(0xffffffffu, oddl ? a[1] : a[3], 1);
                float gi, gf, gg, go;
                if (!oddl) { gi = a[0]; gf = a[1]; gg = s0;   go = s1;   }  // row g
                else       { gi = s0;   gf = s1;   gg = a[2]; go = a[3]; }  // row g+8
                int co = cobase + nt * 2;
                float4 bv = *(const float4*)&d_biasT[co * 4];
                gi += bv.x; gf += bv.y; gg += bv.z; go += bv.w;
                if (has_y) {
                    float4 yv = *(const float4*)&d_Y[ybase + co * 4];
                    gi += yv.x; gf += yv.y; gg += yv.z; go += yv.w;
                }
                float si = fast_sig(gi), sf = fast_sig(gf), so = fast_sig(go);
                float cn = sf * cst[mt][nt] + si * fast_tanh(gg);
                float hv = so * fast_tanh(cn);
                cst[mt][nt] = cn;
                d_hs[((size_t)t * MROWS + r) * NC + co] = hv;
                HO[r * NC + co] = __float2half(hv);
            }
        }

        grid_sync_sw();   // HO complete before next step's A loads
    }
}

// ---------------- ygemm: d_Y = X @ W2 (fp16 mma, 3-stage) ----------------
__global__ void __launch_bounds__(256, 1) ygemm_mma() {
    uint32_t sbase = smem_u32(smem);
    int tid = threadIdx.x;
    int lane = tid & 31, wid = tid >> 5;
    int warp_m = wid & 1, warp_n = wid >> 1;
    int n0 = blockIdx.x * 128;
    int r0 = blockIdx.y * 128;

    float acc[4][4][4] = {};

    auto issue = [&](int c) {
        int buf = c % NSTAGE;
        int kk0 = c * 64;
        uint32_t aoff = sbase + buf * A_STAGE_H * 2;
        uint32_t boff = sbase + (NSTAGE + buf) * A_STAGE_H * 2;
#pragma unroll
        for (int it = 0; it < 4; it++) {
            int u = it * 256 + tid;
            int row = u >> 3, k8 = u & 7;
            cp16(aoff + (row * LDS_H + k8 * 8) * 2,
                 &d_Xh[(size_t)(r0 + row) * KK_Y + kk0 + k8 * 8], true);
        }
#pragma unroll
        for (int it = 0; it < 4; it++) {
            int u = it * 256 + tid;
            int row = u >> 3, k8 = u & 7;
            cp16(boff + (row * LDS_H + k8 * 8) * 2,
                 &d_W2h[(size_t)(n0 + row) * KK_Y + kk0 + k8 * 8], true);
        }
        cp_commit();
    };

    int rsel = lane & 15, hsel = lane >> 4;
    int bn = (lane & 7), bh = (lane >> 3) & 1, btile = lane >> 4;

    issue(0);
    issue(1);
#pragma unroll
    for (int c = 0; c < NCH_Y; c++) {
        if (c + 1 < NCH_Y) cp_wait<1>();
        else               cp_wait<0>();
        __syncthreads();
        if (c + 2 < NCH_Y) issue(c + 2);
        uint32_t sA = sbase + (c % NSTAGE) * A_STAGE_H * 2;
        uint32_t sB = sbase + (NSTAGE + c % NSTAGE) * A_STAGE_H * 2;
#pragma unroll
        for (int kc = 0; kc < 4; kc++) {
            uint32_t bfr[2][4];
#pragma unroll
            for (int p = 0; p < 2; p++) {
                uint32_t addr = sB + ((warp_n * 32 + p * 16 + btile * 8 + bn) * LDS_H
                                      + kc * 16 + bh * 8) * 2;
                ldm_x4(bfr[p], addr);
            }
#pragma unroll
            for (int mt = 0; mt < 4; mt++) {
                uint32_t af[4];
                uint32_t addr = sA + ((warp_m * 64 + mt * 16 + rsel) * LDS_H
                                      + kc * 16 + hsel * 8) * 2;
                ldm_x4(af, addr);
#pragma unroll
                for (int nt = 0; nt < 4; nt++)
                    mma16816(acc[mt][nt], af, &bfr[nt >> 1][(nt & 1) * 2]);
            }
        }
    }

    // epilogue: store raw gates
    int g4 = lane >> 2;
    int col = n0 + warp_n * 32 + 2 * (lane & 3);
    int rA0 = r0 + warp_m * 64 + g4;
#pragma unroll
    for (int mt = 0; mt < 4; mt++) {
#pragma unroll
        for (int nt = 0; nt < 4; nt++) {
            float* a = acc[mt][nt];
            int cc = col + nt * 8;
            size_t pA = (size_t)(rA0 + mt * 16) * NGO + cc;
            size_t pB = (size_t)(rA0 + mt * 16 + 8) * NGO + cc;
            *(float2*)&d_Y[pA] = make_float2(a[0], a[1]);
            *(float2*)&d_Y[pB] = make_float2(a[2], a[3]);
        }
    }
}

// ---------------- output assembly (validated) ----------------
__global__ void __launch_bounds__(256) output_kernel(float* __restrict__ out) {
    __shared__ float tile[127 * 65];
    int c2 = blockIdx.x, b = blockIdx.y;
    int tid = threadIdx.x;
    int hi = c2 >> 2;
    int coL = (c2 & 3) * 64;
    int rL = b * 64 + hi;
    for (int e = tid; e < 127 * 64; e += 256) {
        int tt = e >> 6, j = e & 63;
        tile[tt * 65 + j] = d_hs[((size_t)tt * MROWS + rL) * NC + coL + j];
    }
    __syncthreads();
    float rl[16];
#pragma unroll
    for (int it = 0; it < 16; it++) {
        int o = it * 256 + tid;
        int h2 = o >> 6, ww = o & 63;
        rl[it] = tile[(h2 + ww) * 65 + h2];
    }
    __syncthreads();
    int rR = 1024 + b * 64 + hi;
    for (int e = tid; e < 127 * 64; e += 256) {
        int tt = e >> 6, j = e & 63;
        tile[tt * 65 + j] = d_hs[((size_t)tt * MROWS + rR) * NC + coL + j];
    }
    __syncthreads();
    float* ob = out + ((size_t)(b * 256 + c2)) * 64 * 64;
#pragma unroll
    for (int it = 0; it < 16; it++) {
        int o = it * 256 + tid;
        int h2 = o >> 6, ww = o & 63;
        float rv = (h2 > 0) ? tile[(h2 + 62 - ww) * 65 + (h2 - 1)] : 0.f;
        ob[o] = rl[it] + rv;
    }
}

// ---------------- launch ----------------
extern "C" void kernel_launch(void* const* d_in, const int* in_sizes, int n_in,
                              void* d_out, int out_size) {
    const float* x     = (const float*)d_in[0];
    const float* w_i2s = (const float*)d_in[1];
    const float* b_i2s = (const float*)d_in[2];
    const float* w_ih  = (const float*)d_in[3];
    const float* b_ih  = (const float*)d_in[4];
    const float* b_hh  = (const float*)d_in[5];
    const float* k0    = (const float*)d_in[6];
    const float* k1    = (const float*)d_in[7];
    const float* b_s2s = (const float*)d_in[8];
    float* out = (float*)d_out;

    cudaFuncSetAttribute(step_persist, cudaFuncAttributeMaxDynamicSharedMemorySize, SMEM_STEP);
    cudaFuncSetAttribute(ygemm_mma,    cudaFuncAttributeMaxDynamicSharedMemorySize, SMEM_Y);

    prep_A  <<<dim3(32, 16), dim3(32, 32)>>>(w_ih, k0, k1);
    prep_W2 <<<dim3(32, 8),  dim3(32, 32)>>>(w_ih, w_i2s);
    prep_bias<<<1, 1024>>>(w_ih, b_ih, b_hh, b_i2s, b_s2s);
    pack_W  <<<(NGO * KK_STEP + 255) / 256, 256>>>();
    pack_W2 <<<(NGO * KK_Y + 255) / 256, 256>>>();
    pack_X  <<<dim3(128, 8, 16), dim3(32, 32)>>>(x);
    init_state<<<(MROWS * NC + 255) / 256, 256>>>();

    ygemm_mma<<<dim3(8, 512), 256, SMEM_Y>>>();

    step_persist<<<dim3(8, 16), 256, SMEM_STEP>>>();

    output_kernel<<<dim3(256, 16), 256>>>(out);
}

// round 10
// speedup vs baseline: 5.8731x; 1.0788x over previous
#include <cuda_runtime.h>
#include <cuda_fp16.h>
#include <math.h>
#include <stdint.h>

// ---------------- problem constants ----------------
#define WD    127
#define NB    16
#define NH    64
#define NW    64
#define NC    256
#define MROWS 2048
#define NGO   1024
#define YROWS 65536        // NB*NH*NW
#define KK_STEP 512        // fp16 single-term
#define KK_Y    256
#define NCH_STEP 8         // KK_STEP / 64
#define NCH_Y    4
#define LDS_H   72         // A smem row stride in halves (144B, conflict-free ldmatrix)
#define A_STAGE_H (128 * LDS_H)          // 9216 halves per A stage
#define NSTAGE  3

// persistent step kernel smem: 3 A stages + resident B slice
#define BLDS    520                      // B row stride in halves (1040B)
#define SM_B_H  (NSTAGE * A_STAGE_H)     // B starts at 27648 halves
#define SMEM_STEP ((SM_B_H + 128 * BLDS) * 2)   // 188416 bytes

// ygemm smem: 3 A stages + 3 B stages
#define SMEM_Y  (2 * NSTAGE * A_STAGE_H * 2)    // 110592 bytes

#define NBLK_STEP 128    // 8 x 16 grid, co-resident (1 CTA/SM)
#define NRB 16           // row-blocks

// ---------------- persistent device scratch ----------------
__device__ __align__(128) __half d_Yh[(size_t)YROWS * NGO];            // 134 MB
__device__ __align__(128) __half d_hs16[(size_t)(WD + 1) * MROWS * NC]; // full H history, 134 MB
__device__ __align__(128) float d_AcatT[512 * NGO];
__device__ __align__(128) float d_W2T[256 * NGO];
__device__ __align__(128) float d_biasT[NGO];
__device__ __align__(128) __half d_Wh[NGO * KK_STEP];        // [gp][k]
__device__ __align__(128) __half d_W2h[NGO * KK_Y];          // [gp][k]
__device__ __align__(128) __half d_Xh[(size_t)YROWS * KK_Y]; // [r][ci]
__device__ unsigned g_cnt[WD * NRB];                          // per-(step,rowblock) arrivals

__device__ __forceinline__ int go_of_gp(int gp) { return (gp & 3) * 256 + (gp >> 2); }

// ---------------- baseline-PTX helpers (compile under compute_103) ----------------
__device__ __forceinline__ uint32_t smem_u32(const void* p) {
    uint32_t a;
    asm("{ .reg .u64 t; cvta.to.shared.u64 t, %1; cvt.u32.u64 %0, t; }" : "=r"(a) : "l"(p));
    return a;
}
__device__ __forceinline__ void cp16(uint32_t dst, const void* src, bool pred) {
    int sz = pred ? 16 : 0;   // src-size 0 -> 16B zero-fill
    asm volatile("cp.async.cg.shared.global [%0], [%1], 16, %2;"
                 :: "r"(dst), "l"(src), "r"(sz) : "memory");
}
__device__ __forceinline__ void cp_commit() { asm volatile("cp.async.commit_group;" ::: "memory"); }
template <int N>
__device__ __forceinline__ void cp_wait() { asm volatile("cp.async.wait_group %0;" :: "n"(N) : "memory"); }

__device__ __forceinline__ void ldm_x4(uint32_t* r, uint32_t addr) {
    asm volatile("ldmatrix.sync.aligned.m8n8.x4.shared.b16 {%0,%1,%2,%3}, [%4];"
                 : "=r"(r[0]), "=r"(r[1]), "=r"(r[2]), "=r"(r[3]) : "r"(addr));
}
__device__ __forceinline__ void mma16816(float* c, const uint32_t* a, const uint32_t* b) {
    asm volatile("mma.sync.aligned.m16n8k16.row.col.f32.f16.f16.f32 "
                 "{%0,%1,%2,%3}, {%4,%5,%6,%7}, {%8,%9}, {%0,%1,%2,%3};"
                 : "+f"(c[0]), "+f"(c[1]), "+f"(c[2]), "+f"(c[3])
                 : "r"(a[0]), "r"(a[1]), "r"(a[2]), "r"(a[3]), "r"(b[0]), "r"(b[1]));
}
__device__ __forceinline__ float fast_tanh(float x) {
    x = fminf(fmaxf(x, -15.f), 15.f);
    float e = __expf(2.f * x);
    return (e - 1.f) / (e + 1.f);
}
__device__ __forceinline__ float fast_sig(float x) { return 1.f / (1.f + __expf(-x)); }

extern __shared__ __align__(1024) __half smem[];

// ---------------- prep kernels (fp32 weight fusion) ----------------
__global__ void prep_A(const float* __restrict__ w_ih,
                       const float* __restrict__ k0,
                       const float* __restrict__ k1) {
    __shared__ float Wt[32][33];
    __shared__ float Ks[32][33];
    int x = threadIdx.x, y = threadIdx.y;
    int gp0 = blockIdx.x * 32, kb0 = blockIdx.y * 32;
    const float* ksel = (kb0 < 256) ? k0 : k1;
    int j0 = kb0 & 255;
    float acc = 0.f;
    for (int c0 = 0; c0 < 256; c0 += 32) {
        int go = go_of_gp(gp0 + y);
        Wt[x][y] = w_ih[go * 256 + c0 + x];
        Ks[y][x] = ksel[(c0 + y) * 256 + j0 + x];
        __syncthreads();
#pragma unroll
        for (int cc = 0; cc < 32; cc++) acc += Wt[cc][x] * Ks[cc][y];
        __syncthreads();
    }
    d_AcatT[(kb0 + y) * NGO + gp0 + x] = acc;
}

__global__ void prep_W2(const float* __restrict__ w_ih,
                        const float* __restrict__ w_i2s) {
    __shared__ float Wt[32][33];
    __shared__ float Ms[32][33];
    int x = threadIdx.x, y = threadIdx.y;
    int gp0 = blockIdx.x * 32, ci0 = blockIdx.y * 32;
    float acc = 0.f;
    for (int c0 = 0; c0 < 256; c0 += 32) {
        int go = go_of_gp(gp0 + y);
        Wt[x][y] = w_ih[go * 256 + c0 + x];
        int ci = ci0 + x, c = c0 + y;
        float m = ((ci % 3) <= (c % 3)) ? 1.f : 0.f;
        Ms[y][x] = w_i2s[c * 256 + ci] * m;
        __syncthreads();
#pragma unroll
        for (int cc = 0; cc < 32; cc++) acc += Wt[cc][x] * Ms[cc][y];
        __syncthreads();
    }
    d_W2T[(ci0 + y) * NGO + gp0 + x] = acc;
}

__global__ void prep_bias(const float* __restrict__ w_ih,
                          const float* __restrict__ b_ih,
                          const float* __restrict__ b_hh,
                          const float* __restrict__ b_i2s,
                          const float* __restrict__ b_s2s) {
    int gp = threadIdx.x;
    int go = go_of_gp(gp);
    float s = b_ih[go] + b_hh[go];
    for (int c = 0; c < 256; c++)
        s += w_ih[go * 256 + c] * (b_i2s[c] + b_s2s[c]);
    d_biasT[gp] = s;
}

// ---------------- fp16 packing ----------------
__global__ void pack_W() {
    int i = blockIdx.x * blockDim.x + threadIdx.x;
    if (i >= NGO * KK_STEP) return;
    int gp = i / KK_STEP, k = i % KK_STEP;
    d_Wh[i] = __float2half(d_AcatT[k * NGO + gp]);
}

__global__ void pack_W2() {
    int i = blockIdx.x * blockDim.x + threadIdx.x;
    if (i >= NGO * KK_Y) return;
    int gp = i / KK_Y, k = i % KK_Y;
    d_W2h[i] = __float2half(d_W2T[k * NGO + gp]);
}

__global__ void pack_X(const float* __restrict__ x) {
    __shared__ float tile[32][33];
    int tx = threadIdx.x, ty = threadIdx.y;
    int hw0 = blockIdx.x * 32, ci0 = blockIdx.y * 32, b = blockIdx.z;
    tile[ty][tx] = x[((size_t)(b * 256 + ci0 + ty)) * 4096 + hw0 + tx];
    __syncthreads();
    float v = tile[tx][ty];
    size_t row = (size_t)(b * 4096 + hw0 + ty);
    d_Xh[row * KK_Y + ci0 + tx] = __float2half(v);
}

__global__ void init_state() {
    int i = blockIdx.x * blockDim.x + threadIdx.x;
    if (i < MROWS * NC) d_hs16[i] = __float2half(0.f);   // H history slot 0 (t=0 input)
    if (i < WD * NRB) g_cnt[i] = 0;                      // flow counters
}

// ---------------- persistent step kernel ----------------
// Grid (8,16) x 256 thr. B weights resident in smem; C state in registers;
// flow-dependency sync: CTA at step t spins on cnt[t-1][rb] (and rb+1) == 8.
__global__ void __launch_bounds__(256, 1) step_persist() {
    uint32_t sbase = smem_u32(smem);
    int tid = threadIdx.x;
    int lane = tid & 31, wid = tid >> 5;
    int warp_m = wid & 1, warp_n = wid >> 1;
    int n0 = blockIdx.x * 128;   // gate-col base
    int rb = blockIdx.y;         // row-block
    int r0 = rb * 128;           // row base
    uint32_t sB = sbase + SM_B_H * 2;

    // ---- one-time B fill: 128 rows x 512 k halves ----
#pragma unroll
    for (int it = 0; it < 32; it++) {
        int u = it * 256 + tid;
        int row = u >> 6, k8 = u & 63;
        cp16(sB + (row * BLDS + k8 * 8) * 2,
             &d_Wh[(size_t)(n0 + row) * KK_STEP + k8 * 8], true);
    }
    cp_commit();
    cp_wait<0>();
    __syncthreads();

    // fixed epilogue mapping (step-invariant)
    int g4 = lane >> 2;
    bool oddl = (lane & 1);
    int rbase = r0 + warp_m * 64 + g4 + (oddl ? 8 : 0);
    int cobase = (n0 >> 2) + warp_n * 8 + ((lane >> 1) & 1);
    int rsel = lane & 15, hsel = lane >> 4;                        // A ldmatrix lanes
    int bn = (lane & 7), bh = (lane >> 3) & 1, btile = lane >> 4;  // B ldmatrix lanes

    float cst[4][4] = {};   // cell state in registers for the whole scan

    for (int t = 0; t < WD; t++) {
        const __half* Hin = d_hs16 + (size_t)t * MROWS * NC;
        __half* HO = d_hs16 + (size_t)(t + 1) * MROWS * NC;

        // ---- flow wait: producers of H(t) = step t-1, row-blocks rb, rb+1 ----
        if (t > 0) {
            volatile unsigned* cp0 = &g_cnt[(t - 1) * NRB + rb];
            if (tid == 0) { while (*cp0 < 8u) __nanosleep(32); }
            if (tid == 1 && rb + 1 < NRB) {
                volatile unsigned* cp1 = &g_cnt[(t - 1) * NRB + rb + 1];
                while (*cp1 < 8u) __nanosleep(32);
            }
            __syncthreads();
        }

        float acc[4][4][4] = {};

        auto issueA = [&](int c) {
            int buf = c % NSTAGE;
            int kk0 = c * 64;
            bool shifted = kk0 >= 256;     // Hcat second half -> row r+1
            int kb = kk0 & 255;
            uint32_t aoff = sbase + buf * A_STAGE_H * 2;
#pragma unroll
            for (int it = 0; it < 4; it++) {
                int u = it * 256 + tid;
                int row = u >> 3, k8 = u & 7;
                int rg = r0 + row;
                bool pred = !shifted || ((rg & 1023) != 1023);
                int rs = shifted ? min(rg + 1, MROWS - 1) : rg;
                cp16(aoff + (row * LDS_H + k8 * 8) * 2,
                     &Hin[(size_t)rs * NC + kb + k8 * 8], pred);
            }
            cp_commit();
        };

        issueA(0);
        issueA(1);
#pragma unroll
        for (int c = 0; c < NCH_STEP; c++) {
            if (c + 1 < NCH_STEP) cp_wait<1>();
            else                  cp_wait<0>();
            __syncthreads();
            if (c + 2 < NCH_STEP) issueA(c + 2);
            uint32_t sA = sbase + (c % NSTAGE) * A_STAGE_H * 2;
#pragma unroll
            for (int kc = 0; kc < 4; kc++) {
                int kabs = c * 64 + kc * 16 + bh * 8;
                uint32_t bfr[2][4];
#pragma unroll
                for (int p = 0; p < 2; p++) {
                    uint32_t addr = sB + ((warp_n * 32 + p * 16 + btile * 8 + bn) * BLDS
                                          + kabs) * 2;
                    ldm_x4(bfr[p], addr);
                }
#pragma unroll
                for (int mt = 0; mt < 4; mt++) {
                    uint32_t af[4];
                    uint32_t addr = sA + ((warp_m * 64 + mt * 16 + rsel) * LDS_H
                                          + kc * 16 + hsel * 8) * 2;
                    ldm_x4(af, addr);
#pragma unroll
                    for (int nt = 0; nt < 4; nt++)
                        mma16816(acc[mt][nt], af, &bfr[nt >> 1][(nt & 1) * 2]);
                }
            }
        }

        // ---- epilogue: pair-exchange + fused LSTM cell ----
#pragma unroll
        for (int mt = 0; mt < 4; mt++) {
            int r = rbase + mt * 16;
            int dir = r >> 10, bhv = r & 1023, bb = bhv >> 6, hh = bhv & 63;
            int dg = t - hh;
            bool has_y = (dg >= 0 && dg < 64);
            size_t ybase = 0;
            if (has_y) {
                int ww = dir ? (63 - dg) : dg;
                ybase = (size_t)((bb * 64 + hh) * 64 + ww) * NGO;
            }
#pragma unroll
            for (int nt = 0; nt < 4; nt++) {
                float* a = acc[mt][nt];
                float s0 = __shfl_xor_sync(0xffffffffu, oddl ? a[0] : a[2], 1);
                float s1 = __shfl_xor_sync(0xffffffffu, oddl ? a[1] : a[3], 1);
                float gi, gf, gg, go;
                if (!oddl) { gi = a[0]; gf = a[1]; gg = s0;   go = s1;   }  // row g
                else       { gi = s0;   gf = s1;   gg = a[2]; go = a[3]; }  // row g+8
                int co = cobase + nt * 2;
                float4 bv = *(const float4*)&d_biasT[co * 4];
                gi += bv.x; gf += bv.y; gg += bv.z; go += bv.w;
                if (has_y) {
                    const __half2* yp = (const __half2*)&d_Yh[ybase + co * 4];
                    float2 y01 = __half22float2(yp[0]);
                    float2 y23 = __half22float2(yp[1]);
                    gi += y01.x; gf += y01.y; gg += y23.x; go += y23.y;
                }
                float si = fast_sig(gi), sf = fast_sig(gf), so = fast_sig(go);
                float cn = sf * cst[mt][nt] + si * fast_tanh(gg);
                float hv = so * fast_tanh(cn);
                cst[mt][nt] = cn;
                HO[(size_t)r * NC + co] = __float2half(hv);
            }
        }

        // ---- arrive: all this CTA's H(t+1) writes done ----
        __syncthreads();
        if (tid == 0) {
            __threadfence();
            atomicAdd(&g_cnt[t * NRB + rb], 1u);
        }
    }
}

// ---------------- ygemm: d_Yh = X @ W2 (fp16 mma, 3-stage) ----------------
__global__ void __launch_bounds__(256, 1) ygemm_mma() {
    uint32_t sbase = smem_u32(smem);
    int tid = threadIdx.x;
    int lane = tid & 31, wid = tid >> 5;
    int warp_m = wid & 1, warp_n = wid >> 1;
    int n0 = blockIdx.x * 128;
    int r0 = blockIdx.y * 128;

    float acc[4][4][4] = {};

    auto issue = [&](int c) {
        int buf = c % NSTAGE;
        int kk0 = c * 64;
        uint32_t aoff = sbase + buf * A_STAGE_H * 2;
        uint32_t boff = sbase + (NSTAGE + buf) * A_STAGE_H * 2;
#pragma unroll
        for (int it = 0; it < 4; it++) {
            int u = it * 256 + tid;
            int row = u >> 3, k8 = u & 7;
            cp16(aoff + (row * LDS_H + k8 * 8) * 2,
                 &d_Xh[(size_t)(r0 + row) * KK_Y + kk0 + k8 * 8], true);
        }
#pragma unroll
        for (int it = 0; it < 4; it++) {
            int u = it * 256 + tid;
            int row = u >> 3, k8 = u & 7;
            cp16(boff + (row * LDS_H + k8 * 8) * 2,
                 &d_W2h[(size_t)(n0 + row) * KK_Y + kk0 + k8 * 8], true);
        }
        cp_commit();
    };

    int rsel = lane & 15, hsel = lane >> 4;
    int bn = (lane & 7), bh = (lane >> 3) & 1, btile = lane >> 4;

    issue(0);
    issue(1);
#pragma unroll
    for (int c = 0; c < NCH_Y; c++) {
        if (c + 1 < NCH_Y) cp_wait<1>();
        else               cp_wait<0>();
        __syncthreads();
        if (c + 2 < NCH_Y) issue(c + 2);
        uint32_t sA = sbase + (c % NSTAGE) * A_STAGE_H * 2;
        uint32_t sB = sbase + (NSTAGE + c % NSTAGE) * A_STAGE_H * 2;
#pragma unroll
        for (int kc = 0; kc < 4; kc++) {
            uint32_t bfr[2][4];
#pragma unroll
            for (int p = 0; p < 2; p++) {
                uint32_t addr = sB + ((warp_n * 32 + p * 16 + btile * 8 + bn) * LDS_H
                                      + kc * 16 + bh * 8) * 2;
                ldm_x4(bfr[p], addr);
            }
#pragma unroll
            for (int mt = 0; mt < 4; mt++) {
                uint32_t af[4];
                uint32_t addr = sA + ((warp_m * 64 + mt * 16 + rsel) * LDS_H
                                      + kc * 16 + hsel * 8) * 2;
                ldm_x4(af, addr);
#pragma unroll
                for (int nt = 0; nt < 4; nt++)
                    mma16816(acc[mt][nt], af, &bfr[nt >> 1][(nt & 1) * 2]);
            }
        }
    }

    // epilogue: store raw gates as fp16
    int g4 = lane >> 2;
    int col = n0 + warp_n * 32 + 2 * (lane & 3);
    int rA0 = r0 + warp_m * 64 + g4;
#pragma unroll
    for (int mt = 0; mt < 4; mt++) {
#pragma unroll
        for (int nt = 0; nt < 4; nt++) {
            float* a = acc[mt][nt];
            int cc = col + nt * 8;
            size_t pA = (size_t)(rA0 + mt * 16) * NGO + cc;
            size_t pB = (size_t)(rA0 + mt * 16 + 8) * NGO + cc;
            *(__half2*)&d_Yh[pA] = __floats2half2_rn(a[0], a[1]);
            *(__half2*)&d_Yh[pB] = __floats2half2_rn(a[2], a[3]);
        }
    }
}

// ---------------- output assembly (reads fp16 H history) ----------------
__global__ void __launch_bounds__(256) output_kernel(float* __restrict__ out) {
    __shared__ float tile[127 * 65];
    int c2 = blockIdx.x, b = blockIdx.y;
    int tid = threadIdx.x;
    int hi = c2 >> 2;
    int coL = (c2 & 3) * 64;
    int rL = b * 64 + hi;
    for (int e = tid; e < 127 * 64; e += 256) {
        int tt = e >> 6, j = e & 63;
        tile[tt * 65 + j] = __half2float(
            d_hs16[((size_t)(tt + 1) * MROWS + rL) * NC + coL + j]);
    }
    __syncthreads();
    float rl[16];
#pragma unroll
    for (int it = 0; it < 16; it++) {
        int o = it * 256 + tid;
        int h2 = o >> 6, ww = o & 63;
        rl[it] = tile[(h2 + ww) * 65 + h2];
    }
    __syncthreads();
    int rR = 1024 + b * 64 + hi;
    for (int e = tid; e < 127 * 64; e += 256) {
        int tt = e >> 6, j = e & 63;
        tile[tt * 65 + j] = __half2float(
            d_hs16[((size_t)(tt + 1) * MROWS + rR) * NC + coL + j]);
    }
    __syncthreads();
    float* ob = out + ((size_t)(b * 256 + c2)) * 64 * 64;
#pragma unroll
    for (int it = 0; it < 16; it++) {
        int o = it * 256 + tid;
        int h2 = o >> 6, ww = o & 63;
        float rv = (h2 > 0) ? tile[(h2 + 62 - ww) * 65 + (h2 - 1)] : 0.f;
        ob[o] = rl[it] + rv;
    }
}

// ---------------- launch ----------------
extern "C" void kernel_launch(void* const* d_in, const int* in_sizes, int n_in,
                              void* d_out, int out_size) {
    const float* x     = (const float*)d_in[0];
    const float* w_i2s = (const float*)d_in[1];
    const float* b_i2s = (const float*)d_in[2];
    const float* w_ih  = (const float*)d_in[3];
    const float* b_ih  = (const float*)d_in[4];
    const float* b_hh  = (const float*)d_in[5];
    const float* k0    = (const float*)d_in[6];
    const float* k1    = (const float*)d_in[7];
    const float* b_s2s = (const float*)d_in[8];
    float* out = (float*)d_out;

    cudaFuncSetAttribute(step_persist, cudaFuncAttributeMaxDynamicSharedMemorySize, SMEM_STEP);
    cudaFuncSetAttribute(ygemm_mma,    cudaFuncAttributeMaxDynamicSharedMemorySize, SMEM_Y);

    prep_A  <<<dim3(32, 16), dim3(32, 32)>>>(w_ih, k0, k1);
    prep_W2 <<<dim3(32, 8),  dim3(32, 32)>>>(w_ih, w_i2s);
    prep_bias<<<1, 1024>>>(w_ih, b_ih, b_hh, b_i2s, b_s2s);
    pack_W  <<<(NGO * KK_STEP + 255) / 256, 256>>>();
    pack_W2 <<<(NGO * KK_Y + 255) / 256, 256>>>();
    pack_X  <<<dim3(128, 8, 16), dim3(32, 32)>>>(x);
    init_state<<<(MROWS * NC + 255) / 256, 256>>>();

    ygemm_mma<<<dim3(8, 512), 256, SMEM_Y>>>();

    step_persist<<<dim3(8, 16), 256, SMEM_STEP>>>();

    output_kernel<<<dim3(256, 16), 256>>>(out);
}

// round 11
// speedup vs baseline: 6.6474x; 1.1318x over previous
#include <cuda_runtime.h>
#include <cuda_fp16.h>
#include <math.h>
#include <stdint.h>

// ---------------- problem constants ----------------
#define WD    127
#define NB    16
#define NH    64
#define NW    64
#define NC    256
#define MROWS 2048
#define NGO   1024
#define YROWS 65536        // NB*NH*NW
#define KK_STEP 512        // fp16 single-term
#define KK_Y    256
#define NCH_Y    4
#define NRB 16             // row-blocks

// ---- step kernel smem: one A buffer (129 rows x 264 halves) + resident B ----
#define A_LDS   264                       // 528B stride; 528%128=16 -> conflict-free ldmatrix
#define A_H_SZ  (129 * A_LDS)             // 34056 halves
#define SM_B_H  34176                     // B base (128-half aligned)
#define BLDS    520                       // 1040B stride; conflict-free
#define SMEM_STEP ((SM_B_H + 128 * BLDS) * 2)   // 201472 bytes

// ---- ygemm smem: 3 A stages + 3 B stages (64-wide tiles, stride 72) ----
#define LDS_H   72
#define Y_STAGE_H (128 * LDS_H)
#define NSTAGE  3
#define SMEM_Y  (2 * NSTAGE * Y_STAGE_H * 2)    // 110592 bytes

// ---------------- persistent device scratch ----------------
__device__ __align__(128) __half d_Yh[(size_t)YROWS * NGO];             // 134 MB
__device__ __align__(128) __half d_hs16[(size_t)(WD + 1) * MROWS * NC]; // H history, 134 MB
__device__ __align__(128) float d_AcatT[512 * NGO];
__device__ __align__(128) float d_W2T[256 * NGO];
__device__ __align__(128) float d_biasT[NGO];
__device__ __align__(128) __half d_Wh[NGO * KK_STEP];        // [gp][k]
__device__ __align__(128) __half d_W2h[NGO * KK_Y];          // [gp][k]
__device__ __align__(128) __half d_Xh[(size_t)YROWS * KK_Y]; // [r][ci]
__device__ unsigned g_cnt[WD * NRB];                          // per-(step,rowblock) arrivals

__device__ __forceinline__ int go_of_gp(int gp) { return (gp & 3) * 256 + (gp >> 2); }

// ---------------- baseline-PTX helpers ----------------
__device__ __forceinline__ uint32_t smem_u32(const void* p) {
    uint32_t a;
    asm("{ .reg .u64 t; cvta.to.shared.u64 t, %1; cvt.u32.u64 %0, t; }" : "=r"(a) : "l"(p));
    return a;
}
__device__ __forceinline__ void cp16(uint32_t dst, const void* src, bool pred) {
    int sz = pred ? 16 : 0;   // src-size 0 -> 16B zero-fill
    asm volatile("cp.async.cg.shared.global [%0], [%1], 16, %2;"
                 :: "r"(dst), "l"(src), "r"(sz) : "memory");
}
__device__ __forceinline__ void cp_commit() { asm volatile("cp.async.commit_group;" ::: "memory"); }
template <int N>
__device__ __forceinline__ void cp_wait() { asm volatile("cp.async.wait_group %0;" :: "n"(N) : "memory"); }

__device__ __forceinline__ void ldm_x4(uint32_t* r, uint32_t addr) {
    asm volatile("ldmatrix.sync.aligned.m8n8.x4.shared.b16 {%0,%1,%2,%3}, [%4];"
                 : "=r"(r[0]), "=r"(r[1]), "=r"(r[2]), "=r"(r[3]) : "r"(addr));
}
__device__ __forceinline__ void mma16816(float* c, const uint32_t* a, const uint32_t* b) {
    asm volatile("mma.sync.aligned.m16n8k16.row.col.f32.f16.f16.f32 "
                 "{%0,%1,%2,%3}, {%4,%5,%6,%7}, {%8,%9}, {%0,%1,%2,%3};"
                 : "+f"(c[0]), "+f"(c[1]), "+f"(c[2]), "+f"(c[3])
                 : "r"(a[0]), "r"(a[1]), "r"(a[2]), "r"(a[3]), "r"(b[0]), "r"(b[1]));
}
__device__ __forceinline__ float fast_tanh(float x) {
    x = fminf(fmaxf(x, -15.f), 15.f);
    float e = __expf(2.f * x);
    return (e - 1.f) / (e + 1.f);
}
__device__ __forceinline__ float fast_sig(float x) { return 1.f / (1.f + __expf(-x)); }

extern __shared__ __align__(1024) __half smem[];

// ---------------- prep kernels (fp32 weight fusion) ----------------
__global__ void prep_A(const float* __restrict__ w_ih,
                       const float* __restrict__ k0,
                       const float* __restrict__ k1) {
    __shared__ float Wt[32][33];
    __shared__ float Ks[32][33];
    int x = threadIdx.x, y = threadIdx.y;
    int gp0 = blockIdx.x * 32, kb0 = blockIdx.y * 32;
    const float* ksel = (kb0 < 256) ? k0 : k1;
    int j0 = kb0 & 255;
    float acc = 0.f;
    for (int c0 = 0; c0 < 256; c0 += 32) {
        int go = go_of_gp(gp0 + y);
        Wt[x][y] = w_ih[go * 256 + c0 + x];
        Ks[y][x] = ksel[(c0 + y) * 256 + j0 + x];
        __syncthreads();
#pragma unroll
        for (int cc = 0; cc < 32; cc++) acc += Wt[cc][x] * Ks[cc][y];
        __syncthreads();
    }
    d_AcatT[(kb0 + y) * NGO + gp0 + x] = acc;
}

__global__ void prep_W2(const float* __restrict__ w_ih,
                        const float* __restrict__ w_i2s) {
    __shared__ float Wt[32][33];
    __shared__ float Ms[32][33];
    int x = threadIdx.x, y = threadIdx.y;
    int gp0 = blockIdx.x * 32, ci0 = blockIdx.y * 32;
    float acc = 0.f;
    for (int c0 = 0; c0 < 256; c0 += 32) {
        int go = go_of_gp(gp0 + y);
        Wt[x][y] = w_ih[go * 256 + c0 + x];
        int ci = ci0 + x, c = c0 + y;
        float m = ((ci % 3) <= (c % 3)) ? 1.f : 0.f;
        Ms[y][x] = w_i2s[c * 256 + ci] * m;
        __syncthreads();
#pragma unroll
        for (int cc = 0; cc < 32; cc++) acc += Wt[cc][x] * Ms[cc][y];
        __syncthreads();
    }
    d_W2T[(ci0 + y) * NGO + gp0 + x] = acc;
}

__global__ void prep_bias(const float* __restrict__ w_ih,
                          const float* __restrict__ b_ih,
                          const float* __restrict__ b_hh,
                          const float* __restrict__ b_i2s,
                          const float* __restrict__ b_s2s) {
    int gp = threadIdx.x;
    int go = go_of_gp(gp);
    float s = b_ih[go] + b_hh[go];
    for (int c = 0; c < 256; c++)
        s += w_ih[go * 256 + c] * (b_i2s[c] + b_s2s[c]);
    d_biasT[gp] = s;
}

// ---------------- fp16 packing ----------------
__global__ void pack_W() {
    int i = blockIdx.x * blockDim.x + threadIdx.x;
    if (i >= NGO * KK_STEP) return;
    int gp = i / KK_STEP, k = i % KK_STEP;
    d_Wh[i] = __float2half(d_AcatT[k * NGO + gp]);
}

__global__ void pack_W2() {
    int i = blockIdx.x * blockDim.x + threadIdx.x;
    if (i >= NGO * KK_Y) return;
    int gp = i / KK_Y, k = i % KK_Y;
    d_W2h[i] = __float2half(d_W2T[k * NGO + gp]);
}

__global__ void pack_X(const float* __restrict__ x) {
    __shared__ float tile[32][33];
    int tx = threadIdx.x, ty = threadIdx.y;
    int hw0 = blockIdx.x * 32, ci0 = blockIdx.y * 32, b = blockIdx.z;
    tile[ty][tx] = x[((size_t)(b * 256 + ci0 + ty)) * 4096 + hw0 + tx];
    __syncthreads();
    float v = tile[tx][ty];
    size_t row = (size_t)(b * 4096 + hw0 + ty);
    d_Xh[row * KK_Y + ci0 + tx] = __float2half(v);
}

__global__ void init_state() {
    int i = blockIdx.x * blockDim.x + threadIdx.x;
    if (i < MROWS * NC) d_hs16[i] = __float2half(0.f);   // H slot 0
    if (i < WD * NRB) g_cnt[i] = 0;
}

// ---------------- persistent step kernel ----------------
// Grid (8,16) x 256 thr. B resident in smem; single A buffer/step (129 rows);
// Y prefetched to registers before the flow wait; C state in registers.
__global__ void __launch_bounds__(256, 1) step_persist() {
    uint32_t sbase = smem_u32(smem);
    int tid = threadIdx.x;
    int lane = tid & 31, wid = tid >> 5;
    int warp_m = wid & 1, warp_n = wid >> 1;
    int n0 = blockIdx.x * 128;   // gate-col base
    int rb = blockIdx.y;         // row-block
    int r0 = rb * 128;
    uint32_t sA = sbase;
    uint32_t sB = sbase + SM_B_H * 2;

    // ---- one-time B fill: 128 rows x 512 k halves ----
#pragma unroll
    for (int it = 0; it < 32; it++) {
        int u = it * 256 + tid;
        int row = u >> 6, k8 = u & 63;
        cp16(sB + (row * BLDS + k8 * 8) * 2,
             &d_Wh[(size_t)(n0 + row) * KK_STEP + k8 * 8], true);
    }
    cp_commit();
    cp_wait<0>();
    __syncthreads();

    // fixed epilogue mapping (step-invariant)
    int g4 = lane >> 2;
    bool oddl = (lane & 1);
    int rbase = r0 + warp_m * 64 + g4 + (oddl ? 8 : 0);
    int cobase = (n0 >> 2) + warp_n * 8 + ((lane >> 1) & 1);
    int rsel = lane & 15, hsel = lane >> 4;                        // A ldmatrix lanes
    int bn = (lane & 7), bh = (lane >> 3) & 1, btile = lane >> 4;  // B ldmatrix lanes
    bool row128_ok = ((rb & 7) != 7);   // row r0+128 valid (not a dir/global boundary)

    float cst[4][4] = {};

    for (int t = 0; t < WD; t++) {
        const __half* Hin = d_hs16 + (size_t)t * MROWS * NC;
        __half* HO = d_hs16 + (size_t)(t + 1) * MROWS * NC;

        // ---- Y prefetch into registers (independent of H -> before flow wait) ----
        uint2 yv[4][4];
#pragma unroll
        for (int mt = 0; mt < 4; mt++) {
            int r = rbase + mt * 16;
            int dir = r >> 10, bhv = r & 1023, bb = bhv >> 6, hh = bhv & 63;
            int dg = t - hh;
            bool has_y = (dg >= 0 && dg < 64);
            size_t ybase = 0;
            if (has_y) {
                int ww = dir ? (63 - dg) : dg;
                ybase = (size_t)((bb * 64 + hh) * 64 + ww) * NGO;
            }
#pragma unroll
            for (int nt = 0; nt < 4; nt++) {
                if (has_y) {
                    int co = cobase + nt * 2;
                    yv[mt][nt] = __ldg((const uint2*)&d_Yh[ybase + co * 4]);
                } else {
                    yv[mt][nt] = make_uint2(0u, 0u);
                }
            }
        }

        // ---- flow wait: producers of H(t) = step t-1, row-blocks rb, rb+1 ----
        if (t > 0) {
            volatile unsigned* cp0 = &g_cnt[(t - 1) * NRB + rb];
            if (tid == 0) { while (*cp0 < 8u) __nanosleep(32); }
            if (tid == 1 && rb + 1 < NRB) {
                volatile unsigned* cp1 = &g_cnt[(t - 1) * NRB + rb + 1];
                while (*cp1 < 8u) __nanosleep(32);
            }
            __syncthreads();
        }

        // ---- A load: 129 rows x 256 halves, once per step ----
#pragma unroll
        for (int it = 0; it < 17; it++) {
            int u = it * 256 + tid;
            if (u < 129 * 32) {
                int row = u >> 5, k8 = u & 31;
                bool pred = (row < 128) || row128_ok;
                int rg = min(r0 + row, MROWS - 1);
                cp16(sA + (row * A_LDS + k8 * 8) * 2,
                     &Hin[(size_t)rg * NC + k8 * 8], pred);
            }
        }
        cp_commit();
        cp_wait<0>();
        __syncthreads();

        // ---- mainloop: 8 K-chunks, no barriers ----
        float acc[4][4][4] = {};
#pragma unroll
        for (int c = 0; c < 8; c++) {
            int row_off = (c >= 4) ? 1 : 0;   // shifted half reads rows+1
            int kb = (c & 3) * 64;
#pragma unroll
            for (int kc = 0; kc < 4; kc++) {
                int kabs = c * 64 + kc * 16 + bh * 8;
                uint32_t bfr[2][4];
#pragma unroll
                for (int p = 0; p < 2; p++) {
                    uint32_t addr = sB + ((warp_n * 32 + p * 16 + btile * 8 + bn) * BLDS
                                          + kabs) * 2;
                    ldm_x4(bfr[p], addr);
                }
#pragma unroll
                for (int mt = 0; mt < 4; mt++) {
                    uint32_t af[4];
                    uint32_t addr = sA + ((row_off + warp_m * 64 + mt * 16 + rsel) * A_LDS
                                          + kb + kc * 16 + hsel * 8) * 2;
                    ldm_x4(af, addr);
#pragma unroll
                    for (int nt = 0; nt < 4; nt++)
                        mma16816(acc[mt][nt], af, &bfr[nt >> 1][(nt & 1) * 2]);
                }
            }
        }

        // ---- epilogue: pair-exchange + fused LSTM cell ----
#pragma unroll
        for (int mt = 0; mt < 4; mt++) {
            int r = rbase + mt * 16;
#pragma unroll
            for (int nt = 0; nt < 4; nt++) {
                float* a = acc[mt][nt];
                float s0 = __shfl_xor_sync(0xffffffffu, oddl ? a[0] : a[2], 1);
                float s1 = __shfl_xor_sync(0xffffffffu, oddl ? a[1] : a[3], 1);
                float gi, gf, gg, go;
                if (!oddl) { gi = a[0]; gf = a[1]; gg = s0;   go = s1;   }  // row g
                else       { gi = s0;   gf = s1;   gg = a[2]; go = a[3]; }  // row g+8
                int co = cobase + nt * 2;
                float4 bv = *(const float4*)&d_biasT[co * 4];
                float2 y01 = __half22float2(*(__half2*)&yv[mt][nt].x);
                float2 y23 = __half22float2(*(__half2*)&yv[mt][nt].y);
                gi += bv.x + y01.x; gf += bv.y + y01.y;
                gg += bv.z + y23.x; go += bv.w + y23.y;
                float si = fast_sig(gi), sf = fast_sig(gf), so = fast_sig(go);
                float cn = sf * cst[mt][nt] + si * fast_tanh(gg);
                float hv = so * fast_tanh(cn);
                cst[mt][nt] = cn;
                HO[(size_t)r * NC + co] = __float2half(hv);
            }
        }

        // ---- arrive ----
        __syncthreads();   // also guards smem A reuse next step
        if (tid == 0) {
            __threadfence();
            atomicAdd(&g_cnt[t * NRB + rb], 1u);
        }
    }
}

// ---------------- ygemm: d_Yh = X @ W2 (fp16 mma, 3-stage) ----------------
__global__ void __launch_bounds__(256, 1) ygemm_mma() {
    uint32_t sbase = smem_u32(smem);
    int tid = threadIdx.x;
    int lane = tid & 31, wid = tid >> 5;
    int warp_m = wid & 1, warp_n = wid >> 1;
    int n0 = blockIdx.x * 128;
    int r0 = blockIdx.y * 128;

    float acc[4][4][4] = {};

    auto issue = [&](int c) {
        int buf = c % NSTAGE;
        int kk0 = c * 64;
        uint32_t aoff = sbase + buf * Y_STAGE_H * 2;
        uint32_t boff = sbase + (NSTAGE + buf) * Y_STAGE_H * 2;
#pragma unroll
        for (int it = 0; it < 4; it++) {
            int u = it * 256 + tid;
            int row = u >> 3, k8 = u & 7;
            cp16(aoff + (row * LDS_H + k8 * 8) * 2,
                 &d_Xh[(size_t)(r0 + row) * KK_Y + kk0 + k8 * 8], true);
        }
#pragma unroll
        for (int it = 0; it < 4; it++) {
            int u = it * 256 + tid;
            int row = u >> 3, k8 = u & 7;
            cp16(boff + (row * LDS_H + k8 * 8) * 2,
                 &d_W2h[(size_t)(n0 + row) * KK_Y + kk0 + k8 * 8], true);
        }
        cp_commit();
    };

    int rsel = lane & 15, hsel = lane >> 4;
    int bn = (lane & 7), bh = (lane >> 3) & 1, btile = lane >> 4;

    issue(0);
    issue(1);
#pragma unroll
    for (int c = 0; c < NCH_Y; c++) {
        if (c + 1 < NCH_Y) cp_wait<1>();
        else               cp_wait<0>();
        __syncthreads();
        if (c + 2 < NCH_Y) issue(c + 2);
        uint32_t sA = sbase + (c % NSTAGE) * Y_STAGE_H * 2;
        uint32_t sB = sbase + (NSTAGE + c % NSTAGE) * Y_STAGE_H * 2;
#pragma unroll
        for (int kc = 0; kc < 4; kc++) {
            uint32_t bfr[2][4];
#pragma unroll
            for (int p = 0; p < 2; p++) {
                uint32_t addr = sB + ((warp_n * 32 + p * 16 + btile * 8 + bn) * LDS_H
                                      + kc * 16 + bh * 8) * 2;
                ldm_x4(bfr[p], addr);
            }
#pragma unroll
            for (int mt = 0; mt < 4; mt++) {
                uint32_t af[4];
                uint32_t addr = sA + ((warp_m * 64 + mt * 16 + rsel) * LDS_H
                                      + kc * 16 + hsel * 8) * 2;
                ldm_x4(af, addr);
#pragma unroll
                for (int nt = 0; nt < 4; nt++)
                    mma16816(acc[mt][nt], af, &bfr[nt >> 1][(nt & 1) * 2]);
            }
        }
    }

    int g4 = lane >> 2;
    int col = n0 + warp_n * 32 + 2 * (lane & 3);
    int rA0 = r0 + warp_m * 64 + g4;
#pragma unroll
    for (int mt = 0; mt < 4; mt++) {
#pragma unroll
        for (int nt = 0; nt < 4; nt++) {
            float* a = acc[mt][nt];
            int cc = col + nt * 8;
            size_t pA = (size_t)(rA0 + mt * 16) * NGO + cc;
            size_t pB = (size_t)(rA0 + mt * 16 + 8) * NGO + cc;
            *(__half2*)&d_Yh[pA] = __floats2half2_rn(a[0], a[1]);
            *(__half2*)&d_Yh[pB] = __floats2half2_rn(a[2], a[3]);
        }
    }
}

// ---------------- output assembly (reads fp16 H history) ----------------
__global__ void __launch_bounds__(256) output_kernel(float* __restrict__ out) {
    __shared__ float tile[127 * 65];
    int c2 = blockIdx.x, b = blockIdx.y;
    int tid = threadIdx.x;
    int hi = c2 >> 2;
    int coL = (c2 & 3) * 64;
    int rL = b * 64 + hi;
    for (int e = tid; e < 127 * 64; e += 256) {
        int tt = e >> 6, j = e & 63;
        tile[tt * 65 + j] = __half2float(
            d_hs16[((size_t)(tt + 1) * MROWS + rL) * NC + coL + j]);
    }
    __syncthreads();
    float rl[16];
#pragma unroll
    for (int it = 0; it < 16; it++) {
        int o = it * 256 + tid;
        int h2 = o >> 6, ww = o & 63;
        rl[it] = tile[(h2 + ww) * 65 + h2];
    }
    __syncthreads();
    int rR = 1024 + b * 64 + hi;
    for (int e = tid; e < 127 * 64; e += 256) {
        int tt = e >> 6, j = e & 63;
        tile[tt * 65 + j] = __half2float(
            d_hs16[((size_t)(tt + 1) * MROWS + rR) * NC + coL + j]);
    }
    __syncthreads();
    float* ob = out + ((size_t)(b * 256 + c2)) * 64 * 64;
#pragma unroll
    for (int it = 0; it < 16; it++) {
        int o = it * 256 + tid;
        int h2 = o >> 6, ww = o & 63;
        float rv = (h2 > 0) ? tile[(h2 + 62 - ww) * 65 + (h2 - 1)] : 0.f;
        ob[o] = rl[it] + rv;
    }
}

// ---------------- launch ----------------
extern "C" void kernel_launch(void* const* d_in, const int* in_sizes, int n_in,
                              void* d_out, int out_size) {
    const float* x     = (const float*)d_in[0];
    const float* w_i2s = (const float*)d_in[1];
    const float* b_i2s = (const float*)d_in[2];
    const float* w_ih  = (const float*)d_in[3];
    const float* b_ih  = (const float*)d_in[4];
    const float* b_hh  = (const float*)d_in[5];
    const float* k0    = (const float*)d_in[6];
    const float* k1    = (const float*)d_in[7];
    const float* b_s2s = (const float*)d_in[8];
    float* out = (float*)d_out;

    cudaFuncSetAttribute(step_persist, cudaFuncAttributeMaxDynamicSharedMemorySize, SMEM_STEP);
    cudaFuncSetAttribute(ygemm_mma,    cudaFuncAttributeMaxDynamicSharedMemorySize, SMEM_Y);

    prep_A  <<<dim3(32, 16), dim3(32, 32)>>>(w_ih, k0, k1);
    prep_W2 <<<dim3(32, 8),  dim3(32, 32)>>>(w_ih, w_i2s);
    prep_bias<<<1, 1024>>>(w_ih, b_ih, b_hh, b_i2s, b_s2s);
    pack_W  <<<(NGO * KK_STEP + 255) / 256, 256>>>();
    pack_W2 <<<(NGO * KK_Y + 255) / 256, 256>>>();
    pack_X  <<<dim3(128, 8, 16), dim3(32, 32)>>>(x);
    init_state<<<(MROWS * NC + 255) / 256, 256>>>();

    ygemm_mma<<<dim3(8, 512), 256, SMEM_Y>>>();

    step_persist<<<dim3(8, 16), 256, SMEM_STEP>>>();

    output_kernel<<<dim3(256, 16), 256>>>(out);
}

// round 15
// speedup vs baseline: 9.4530x; 1.4221x over previous
#include <cuda_runtime.h>
#include <cuda_fp16.h>
#include <math.h>
#include <stdint.h>

// ---------------- problem constants ----------------
#define WD    127
#define NB    16
#define NH    64
#define NW    64
#define NC    256
#define MROWS 2048
#define NGO   1024
#define YROWS 65536        // NB*NH*NW
#define KK_STEP 512        // fp16 single-term
#define KK_Y    256
#define NCH_Y    4
#define NRB 16             // row-blocks

// ---- step kernel smem: A buffer (129 x 264) + resident B + H stage ----
#define A_LDS   264                       // 528B stride; conflict-free ldmatrix
#define SM_B_H  34176                     // B base in halves (A is 129*264=34056)
#define BLDS    520                       // 1040B stride; conflict-free
#define SM_HST_H (SM_B_H + 128 * BLDS)    // 100736 halves
#define HST_LDS 40                        // 80B stride (16B-aligned rows)
#define SMEM_STEP ((SM_HST_H + 128 * HST_LDS) * 2)   // 211712 bytes

// ---- ygemm smem: 3 A stages + 3 B stages ----
#define LDS_H   72
#define Y_STAGE_H (128 * LDS_H)
#define NSTAGE  3
#define SMEM_Y  (2 * NSTAGE * Y_STAGE_H * 2)    // 110592 bytes

// ---------------- persistent device scratch ----------------
__device__ __align__(128) __half d_Yh[(size_t)YROWS * NGO];             // 134 MB
__device__ __align__(128) __half d_hs16[(size_t)(WD + 1) * MROWS * NC]; // H history
__device__ __align__(128) float d_AcatT[512 * NGO];
__device__ __align__(128) float d_W2T[256 * NGO];
__device__ __align__(128) float d_biasT[NGO];
__device__ __align__(128) __half d_Wh[NGO * KK_STEP];        // [gp][k]
__device__ __align__(128) __half d_W2h[NGO * KK_Y];          // [gp][k]
__device__ __align__(128) __half d_Xh[(size_t)YROWS * KK_Y]; // [r][ci]
__device__ unsigned g_cnt[WD * NRB];                          // per-(step,rowblock) arrivals

__device__ __forceinline__ int go_of_gp(int gp) { return (gp & 3) * 256 + (gp >> 2); }

// ---------------- baseline-PTX helpers ----------------
__device__ __forceinline__ uint32_t smem_u32(const void* p) {
    uint32_t a;
    asm("{ .reg .u64 t; cvta.to.shared.u64 t, %1; cvt.u32.u64 %0, t; }" : "=r"(a) : "l"(p));
    return a;
}
__device__ __forceinline__ void cp16(uint32_t dst, const void* src, bool pred) {
    int sz = pred ? 16 : 0;   // src-size 0 -> 16B zero-fill
    asm volatile("cp.async.cg.shared.global [%0], [%1], 16, %2;"
                 :: "r"(dst), "l"(src), "r"(sz) : "memory");
}
__device__ __forceinline__ void cp_commit() { asm volatile("cp.async.commit_group;" ::: "memory"); }
template <int N>
__device__ __forceinline__ void cp_wait() { asm volatile("cp.async.wait_group %0;" :: "n"(N) : "memory"); }

__device__ __forceinline__ void ldm_x4(uint32_t* r, uint32_t addr) {
    asm volatile("ldmatrix.sync.aligned.m8n8.x4.shared.b16 {%0,%1,%2,%3}, [%4];"
                 : "=r"(r[0]), "=r"(r[1]), "=r"(r[2]), "=r"(r[3]) : "r"(addr));
}
__device__ __forceinline__ void mma16816(float* c, const uint32_t* a, const uint32_t* b) {
    asm volatile("mma.sync.aligned.m16n8k16.row.col.f32.f16.f16.f32 "
                 "{%0,%1,%2,%3}, {%4,%5,%6,%7}, {%8,%9}, {%0,%1,%2,%3};"
                 : "+f"(c[0]), "+f"(c[1]), "+f"(c[2]), "+f"(c[3])
                 : "r"(a[0]), "r"(a[1]), "r"(a[2]), "r"(a[3]), "r"(b[0]), "r"(b[1]));
}
// HW tanh (sm_75+ baseline): 1 MUFU op; sigmoid = 0.5*tanh(x/2)+0.5
__device__ __forceinline__ float tanh_ap(float x) {
    float y;
    asm("tanh.approx.f32 %0, %1;" : "=f"(y) : "f"(x));
    return y;
}
__device__ __forceinline__ float sig_ap(float x) {
    return fmaf(0.5f, tanh_ap(0.5f * x), 0.5f);
}

extern __shared__ __align__(1024) __half smem[];

// ---------------- prep kernels (fp32 weight fusion) ----------------
__global__ void prep_A(const float* __restrict__ w_ih,
                       const float* __restrict__ k0,
                       const float* __restrict__ k1) {
    __shared__ float Wt[32][33];
    __shared__ float Ks[32][33];
    int x = threadIdx.x, y = threadIdx.y;
    int gp0 = blockIdx.x * 32, kb0 = blockIdx.y * 32;
    const float* ksel = (kb0 < 256) ? k0 : k1;
    int j0 = kb0 & 255;
    float acc = 0.f;
    for (int c0 = 0; c0 < 256; c0 += 32) {
        int go = go_of_gp(gp0 + y);
        Wt[x][y] = w_ih[go * 256 + c0 + x];
        Ks[y][x] = ksel[(c0 + y) * 256 + j0 + x];
        __syncthreads();
#pragma unroll
        for (int cc = 0; cc < 32; cc++) acc += Wt[cc][x] * Ks[cc][y];
        __syncthreads();
    }
    d_AcatT[(kb0 + y) * NGO + gp0 + x] = acc;
}

__global__ void prep_W2(const float* __restrict__ w_ih,
                        const float* __restrict__ w_i2s) {
    __shared__ float Wt[32][33];
    __shared__ float Ms[32][33];
    int x = threadIdx.x, y = threadIdx.y;
    int gp0 = blockIdx.x * 32, ci0 = blockIdx.y * 32;
    float acc = 0.f;
    for (int c0 = 0; c0 < 256; c0 += 32) {
        int go = go_of_gp(gp0 + y);
        Wt[x][y] = w_ih[go * 256 + c0 + x];
        int ci = ci0 + x, c = c0 + y;
        float m = ((ci % 3) <= (c % 3)) ? 1.f : 0.f;
        Ms[y][x] = w_i2s[c * 256 + ci] * m;
        __syncthreads();
#pragma unroll
        for (int cc = 0; cc < 32; cc++) acc += Wt[cc][x] * Ms[cc][y];
        __syncthreads();
    }
    d_W2T[(ci0 + y) * NGO + gp0 + x] = acc;
}

__global__ void prep_bias(const float* __restrict__ w_ih,
                          const float* __restrict__ b_ih,
                          const float* __restrict__ b_hh,
                          const float* __restrict__ b_i2s,
                          const float* __restrict__ b_s2s) {
    int gp = threadIdx.x;
    int go = go_of_gp(gp);
    float s = b_ih[go] + b_hh[go];
    for (int c = 0; c < 256; c++)
        s += w_ih[go * 256 + c] * (b_i2s[c] + b_s2s[c]);
    d_biasT[gp] = s;
}

// ---------------- fp16 packing ----------------
__global__ void pack_W() {
    int i = blockIdx.x * blockDim.x + threadIdx.x;
    if (i >= NGO * KK_STEP) return;
    int gp = i / KK_STEP, k = i % KK_STEP;
    d_Wh[i] = __float2half(d_AcatT[k * NGO + gp]);
}

__global__ void pack_W2() {
    int i = blockIdx.x * blockDim.x + threadIdx.x;
    if (i >= NGO * KK_Y) return;
    int gp = i / KK_Y, k = i % KK_Y;
    d_W2h[i] = __float2half(d_W2T[k * NGO + gp]);
}

__global__ void pack_X(const float* __restrict__ x) {
    __shared__ float tile[32][33];
    int tx = threadIdx.x, ty = threadIdx.y;
    int hw0 = blockIdx.x * 32, ci0 = blockIdx.y * 32, b = blockIdx.z;
    tile[ty][tx] = x[((size_t)(b * 256 + ci0 + ty)) * 4096 + hw0 + tx];
    __syncthreads();
    float v = tile[tx][ty];
    size_t row = (size_t)(b * 4096 + hw0 + ty);
    d_Xh[row * KK_Y + ci0 + tx] = __float2half(v);
}

__global__ void init_state() {
    int i = blockIdx.x * blockDim.x + threadIdx.x;
    if (i < MROWS * NC) d_hs16[i] = __float2half(0.f);   // H slot 0
    if (i < WD * NRB) g_cnt[i] = 0;
}

// ---------------- persistent step kernel ----------------
// Grid (8,16) x 256 thr. B resident in smem; A loaded in 4 pipelined column
// groups; Y prefetched to regs before flow wait; C in regs; H stores staged
// through smem for coalescing.
__global__ void __launch_bounds__(256, 1) step_persist() {
    uint32_t sbase = smem_u32(smem);
    int tid = threadIdx.x;
    int lane = tid & 31, wid = tid >> 5;
    int warp_m = wid & 1, warp_n = wid >> 1;
    int n0 = blockIdx.x * 128;   // gate-col base
    int rb = blockIdx.y;         // row-block
    int r0 = rb * 128;
    uint32_t sA = sbase;
    uint32_t sB = sbase + SM_B_H * 2;
    __half* hst = smem + SM_HST_H;

    // ---- one-time B fill: 128 rows x 512 k halves ----
#pragma unroll
    for (int it = 0; it < 32; it++) {
        int u = it * 256 + tid;
        int row = u >> 6, k8 = u & 63;
        cp16(sB + (row * BLDS + k8 * 8) * 2,
             &d_Wh[(size_t)(n0 + row) * KK_STEP + k8 * 8], true);
    }
    cp_commit();
    cp_wait<0>();
    __syncthreads();

    // fixed mappings (step-invariant)
    int g4 = lane >> 2;
    bool oddl = (lane & 1);
    int rbase = r0 + warp_m * 64 + g4 + (oddl ? 8 : 0);
    int cobase = (n0 >> 2) + warp_n * 8 + ((lane >> 1) & 1);
    int rl_base = warp_m * 64 + g4 + (oddl ? 8 : 0);                 // CTA-local row
    int cl_base = warp_n * 8 + ((lane >> 1) & 1);                    // CTA-local col
    int rsel = lane & 15, hsel = lane >> 4;                          // A ldmatrix lanes
    int bn = (lane & 7), bh = (lane >> 3) & 1, btile = lane >> 4;    // B ldmatrix lanes
    bool row128_ok = ((rb & 7) != 7);   // row r0+128 valid (not a dir boundary)

    float cst[4][4] = {};

    for (int t = 0; t < WD; t++) {
        const __half* Hin = d_hs16 + (size_t)t * MROWS * NC;
        __half* HO = d_hs16 + (size_t)(t + 1) * MROWS * NC;

        // ---- Y prefetch into registers (independent of H) ----
        uint2 yv[4][4];
#pragma unroll
        for (int mt = 0; mt < 4; mt++) {
            int r = rbase + mt * 16;
            int dir = r >> 10, bhv = r & 1023, bb = bhv >> 6, hh = bhv & 63;
            int dg = t - hh;
            bool has_y = (dg >= 0 && dg < 64);
            size_t ybase = 0;
            if (has_y) {
                int ww = dir ? (63 - dg) : dg;
                ybase = (size_t)((bb * 64 + hh) * 64 + ww) * NGO;
            }
#pragma unroll
            for (int nt = 0; nt < 4; nt++) {
                if (has_y) {
                    int co = cobase + nt * 2;
                    yv[mt][nt] = __ldg((const uint2*)&d_Yh[ybase + co * 4]);
                } else {
                    yv[mt][nt] = make_uint2(0u, 0u);
                }
            }
        }

        // ---- flow wait: producers of H(t) = step t-1, row-blocks rb, rb+1 ----
        if (t > 0) {
            volatile unsigned* cp0 = &g_cnt[(t - 1) * NRB + rb];
            if (tid == 0) { while (*cp0 < 8u) __nanosleep(32); }
            if (tid == 1 && rb + 1 < NRB) {
                volatile unsigned* cp1 = &g_cnt[(t - 1) * NRB + rb + 1];
                while (*cp1 < 8u) __nanosleep(32);
            }
            __syncthreads();
        }

        // ---- A load: 4 column-group commit groups (129 rows x 64 cols each) ----
#pragma unroll
        for (int g = 0; g < 4; g++) {
#pragma unroll
            for (int it = 0; it < 5; it++) {
                int u = it * 256 + tid;
                if (u < 129 * 8) {
                    int row = u >> 3, k8 = (u & 7) + 8 * g;
                    bool pred = (row < 128) || row128_ok;
                    int rg = min(r0 + row, MROWS - 1);
                    cp16(sA + (row * A_LDS + k8 * 8) * 2,
                         &Hin[(size_t)rg * NC + k8 * 8], pred);
                }
            }
            cp_commit();
        }

        // ---- mainloop: chunk pairs (j, j+4) as column group j arrives ----
        float acc[4][4][4] = {};
#pragma unroll
        for (int j = 0; j < 4; j++) {
            if (j == 0)      cp_wait<3>();
            else if (j == 1) cp_wait<2>();
            else if (j == 2) cp_wait<1>();
            else             cp_wait<0>();
            __syncthreads();
#pragma unroll
            for (int half = 0; half < 2; half++) {
                int c = j + half * 4;          // chunk index
                int row_off = half;            // shifted half reads rows+1
                int kb = j * 64;               // A column base
#pragma unroll
                for (int kc = 0; kc < 4; kc++) {
                    int kabs = c * 64 + kc * 16 + bh * 8;
                    uint32_t bfr[2][4];
#pragma unroll
                    for (int p = 0; p < 2; p++) {
                        uint32_t addr = sB + ((warp_n * 32 + p * 16 + btile * 8 + bn) * BLDS
                                              + kabs) * 2;
                        ldm_x4(bfr[p], addr);
                    }
#pragma unroll
                    for (int mt = 0; mt < 4; mt++) {
                        uint32_t af[4];
                        uint32_t addr = sA + ((row_off + warp_m * 64 + mt * 16 + rsel) * A_LDS
                                              + kb + kc * 16 + hsel * 8) * 2;
                        ldm_x4(af, addr);
#pragma unroll
                        for (int nt = 0; nt < 4; nt++)
                            mma16816(acc[mt][nt], af, &bfr[nt >> 1][(nt & 1) * 2]);
                    }
                }
            }
        }

        // ---- epilogue: pair-exchange + fused LSTM cell, stage H in smem ----
#pragma unroll
        for (int mt = 0; mt < 4; mt++) {
#pragma unroll
            for (int nt = 0; nt < 4; nt++) {
                float* a = acc[mt][nt];
                float s0 = __shfl_xor_sync(0xffffffffu, oddl ? a[0] : a[2], 1);
                float s1 = __shfl_xor_sync(0xffffffffu, oddl ? a[1] : a[3], 1);
                float gi, gf, gg, go;
                if (!oddl) { gi = a[0]; gf = a[1]; gg = s0;   go = s1;   }  // row g
                else       { gi = s0;   gf = s1;   gg = a[2]; go = a[3]; }  // row g+8
                int co = cobase + nt * 2;
                float4 bv = *(const float4*)&d_biasT[co * 4];
                float2 y01 = __half22float2(*(__half2*)&yv[mt][nt].x);
                float2 y23 = __half22float2(*(__half2*)&yv[mt][nt].y);
                gi += bv.x + y01.x; gf += bv.y + y01.y;
                gg += bv.z + y23.x; go += bv.w + y23.y;
                float si = sig_ap(gi), sf = sig_ap(gf), so = sig_ap(go);
                float cn = sf * cst[mt][nt] + si * tanh_ap(gg);
                float hv = so * tanh_ap(cn);
                cst[mt][nt] = cn;
                hst[(rl_base + mt * 16) * HST_LDS + cl_base + nt * 2] = __float2half(hv);
            }
        }
        __syncthreads();

        // ---- coalesced H store: 128 rows x 64B ----
#pragma unroll
        for (int it = 0; it < 2; it++) {
            int u = it * 256 + tid;
            int row = u >> 2, q = u & 3;
            uint4 v = *(uint4*)&hst[row * HST_LDS + q * 8];
            *(uint4*)&HO[(size_t)(r0 + row) * NC + (n0 >> 2) + q * 8] = v;
        }

        // ---- arrive ----
        __syncthreads();
        if (tid == 0) {
            __threadfence();
            atomicAdd(&g_cnt[t * NRB + rb], 1u);
        }
    }
}

// ---------------- ygemm: d_Yh = X @ W2 (fp16 mma, 3-stage) ----------------
__global__ void __launch_bounds__(256, 1) ygemm_mma() {
    uint32_t sbase = smem_u32(smem);
    int tid = threadIdx.x;
    int lane = tid & 31, wid = tid >> 5;
    int warp_m = wid & 1, warp_n = wid >> 1;
    int n0 = blockIdx.x * 128;
    int r0 = blockIdx.y * 128;

    float acc[4][4][4] = {};

    auto issue = [&](int c) {
        int buf = c % NSTAGE;
        int kk0 = c * 64;
        uint32_t aoff = sbase + buf * Y_STAGE_H * 2;
        uint32_t boff = sbase + (NSTAGE + buf) * Y_STAGE_H * 2;
#pragma unroll
        for (int it = 0; it < 4; it++) {
            int u = it * 256 + tid;
            int row = u >> 3, k8 = u & 7;
            cp16(aoff + (row * LDS_H + k8 * 8) * 2,
                 &d_Xh[(size_t)(r0 + row) * KK_Y + kk0 + k8 * 8], true);
        }
#pragma unroll
        for (int it = 0; it < 4; it++) {
            int u = it * 256 + tid;
            int row = u >> 3, k8 = u & 7;
            cp16(boff + (row * LDS_H + k8 * 8) * 2,
                 &d_W2h[(size_t)(n0 + row) * KK_Y + kk0 + k8 * 8], true);
        }
        cp_commit();
    };

    int rsel = lane & 15, hsel = lane >> 4;
    int bn = (lane & 7), bh = (lane >> 3) & 1, btile = lane >> 4;

    issue(0);
    issue(1);
#pragma unroll
    for (int c = 0; c < NCH_Y; c++) {
        if (c + 1 < NCH_Y) cp_wait<1>();
        else               cp_wait<0>();
        __syncthreads();
        if (c + 2 < NCH_Y) issue(c + 2);
        uint32_t sA = sbase + (c % NSTAGE) * Y_STAGE_H * 2;
        uint32_t sB = sbase + (NSTAGE + c % NSTAGE) * Y_STAGE_H * 2;
#pragma unroll
        for (int kc = 0; kc < 4; kc++) {
            uint32_t bfr[2][4];
#pragma unroll
            for (int p = 0; p < 2; p++) {
                uint32_t addr = sB + ((warp_n * 32 + p * 16 + btile * 8 + bn) * LDS_H
                                      + kc * 16 + bh * 8) * 2;
                ldm_x4(bfr[p], addr);
            }
#pragma unroll
            for (int mt = 0; mt < 4; mt++) {
                uint32_t af[4];
                uint32_t addr = sA + ((warp_m * 64 + mt * 16 + rsel) * LDS_H
                                      + kc * 16 + hsel * 8) * 2;
                ldm_x4(af, addr);
#pragma unroll
                for (int nt = 0; nt < 4; nt++)
                    mma16816(acc[mt][nt], af, &bfr[nt >> 1][(nt & 1) * 2]);
            }
        }
    }

    int g4 = lane >> 2;
    int col = n0 + warp_n * 32 + 2 * (lane & 3);
    int rA0 = r0 + warp_m * 64 + g4;
#pragma unroll
    for (int mt = 0; mt < 4; mt++) {
#pragma unroll
        for (int nt = 0; nt < 4; nt++) {
            float* a = acc[mt][nt];
            int cc = col + nt * 8;
            size_t pA = (size_t)(rA0 + mt * 16) * NGO + cc;
            size_t pB = (size_t)(rA0 + mt * 16 + 8) * NGO + cc;
            *(__half2*)&d_Yh[pA] = __floats2half2_rn(a[0], a[1]);
            *(__half2*)&d_Yh[pB] = __floats2half2_rn(a[2], a[3]);
        }
    }
}

// ---------------- output assembly (reads fp16 H history) ----------------
__global__ void __launch_bounds__(256) output_kernel(float* __restrict__ out) {
    __shared__ float tile[127 * 65];
    int c2 = blockIdx.x, b = blockIdx.y;
    int tid = threadIdx.x;
    int hi = c2 >> 2;
    int coL = (c2 & 3) * 64;
    int rL = b * 64 + hi;
    for (int e = tid; e < 127 * 64; e += 256) {
        int tt = e >> 6, j = e & 63;
        tile[tt * 65 + j] = __half2float(
            d_hs16[((size_t)(tt + 1) * MROWS + rL) * NC + coL + j]);
    }
    __syncthreads();
    float rl[16];
#pragma unroll
    for (int it = 0; it < 16; it++) {
        int o = it * 256 + tid;
        int h2 = o >> 6, ww = o & 63;
        rl[it] = tile[(h2 + ww) * 65 + h2];
    }
    __syncthreads();
    int rR = 1024 + b * 64 + hi;
    for (int e = tid; e < 127 * 64; e += 256) {
        int tt = e >> 6, j = e & 63;
        tile[tt * 65 + j] = __half2float(
            d_hs16[((size_t)(tt + 1) * MROWS + rR) * NC + coL + j]);
    }
    __syncthreads();
    float* ob = out + ((size_t)(b * 256 + c2)) * 64 * 64;
#pragma unroll
    for (int it = 0; it < 16; it++) {
        int o = it * 256 + tid;
        int h2 = o >> 6, ww = o & 63;
        float rv = (h2 > 0) ? tile[(h2 + 62 - ww) * 65 + (h2 - 1)] : 0.f;
        ob[o] = rl[it] + rv;
    }
}

// ---------------- launch ----------------
extern "C" void kernel_launch(void* const* d_in, const int* in_sizes, int n_in,
                              void* d_out, int out_size) {
    const float* x     = (const float*)d_in[0];
    const float* w_i2s = (const float*)d_in[1];
    const float* b_i2s = (const float*)d_in[2];
    const float* w_ih  = (const float*)d_in[3];
    const float* b_ih  = (const float*)d_in[4];
    const float* b_hh  = (const float*)d_in[5];
    const float* k0    = (const float*)d_in[6];
    const float* k1    = (const float*)d_in[7];
    const float* b_s2s = (const float*)d_in[8];
    float* out = (float*)d_out;

    cudaFuncSetAttribute(step_persist, cudaFuncAttributeMaxDynamicSharedMemorySize, SMEM_STEP);
    cudaFuncSetAttribute(ygemm_mma,    cudaFuncAttributeMaxDynamicSharedMemorySize, SMEM_Y);

    prep_A  <<<dim3(32, 16), dim3(32, 32)>>>(w_ih, k0, k1);
    prep_W2 <<<dim3(32, 8),  dim3(32, 32)>>>(w_ih, w_i2s);
    prep_bias<<<1, 1024>>>(w_ih, b_ih, b_hh, b_i2s, b_s2s);
    pack_W  <<<(NGO * KK_STEP + 255) / 256, 256>>>();
    pack_W2 <<<(NGO * KK_Y + 255) / 256, 256>>>();
    pack_X  <<<dim3(128, 8, 16), dim3(32, 32)>>>(x);
    init_state<<<(MROWS * NC + 255) / 256, 256>>>();

    ygemm_mma<<<dim3(8, 512), 256, SMEM_Y>>>();

    step_persist<<<dim3(8, 16), 256, SMEM_STEP>>>();

    output_kernel<<<dim3(256, 16), 256>>>(out);
}

// round 16
// speedup vs baseline: 10.9839x; 1.1619x over previous
#include <cuda_runtime.h>
#include <cuda_fp16.h>
#include <math.h>
#include <stdint.h>

// ---------------- problem constants ----------------
#define WD    127
#define NB    16
#define NH    64
#define NW    64
#define NC    256
#define MROWS 2048
#define NGO   1024
#define YROWS 65536        // NB*NH*NW
#define KK_STEP 512        // fp16 single-term
#define KK_Y    256
#define NCH_Y    4
#define NRB 16             // row-blocks

// ---- step kernel smem: A buffer (129 x 264) + resident B + H stage ----
#define A_LDS   264                       // 528B stride; conflict-free ldmatrix
#define SM_B_H  34176                     // B base in halves (A is 129*264=34056)
#define BLDS    520                       // 1040B stride; conflict-free
#define SM_HST_H (SM_B_H + 128 * BLDS)    // 100736 halves
#define HST_LDS 40                        // 80B stride (16B-aligned rows)
#define SMEM_STEP ((SM_HST_H + 128 * HST_LDS) * 2)   // 211712 bytes

// ---- ygemm smem: 2 A stages + 2 B stages (2 CTAs/SM) ----
#define LDS_H   72
#define Y_STAGE_H (128 * LDS_H)
#define NSTAGE_Y 2
#define SMEM_Y  (2 * NSTAGE_Y * Y_STAGE_H * 2)    // 73728 bytes

// ---------------- persistent device scratch ----------------
__device__ __align__(128) __half d_Yh[(size_t)YROWS * NGO];             // 134 MB
__device__ __align__(128) __half d_hs16[(size_t)(WD + 1) * MROWS * NC]; // H history
__device__ __align__(128) float d_AcatT[512 * NGO];
__device__ __align__(128) float d_W2T[256 * NGO];
__device__ __align__(128) float d_biasT[NGO];
__device__ __align__(128) __half d_Wh[NGO * KK_STEP];        // [gp][k]
__device__ __align__(128) __half d_W2h[NGO * KK_Y];          // [gp][k]
__device__ __align__(128) __half d_Xh[(size_t)YROWS * KK_Y]; // [r][ci]
__device__ unsigned g_cnt[WD * NRB];                          // per-(step,rowblock) arrivals

__device__ __forceinline__ int go_of_gp(int gp) { return (gp & 3) * 256 + (gp >> 2); }

// ---------------- baseline-PTX helpers ----------------
__device__ __forceinline__ uint32_t smem_u32(const void* p) {
    uint32_t a;
    asm("{ .reg .u64 t; cvta.to.shared.u64 t, %1; cvt.u32.u64 %0, t; }" : "=r"(a) : "l"(p));
    return a;
}
__device__ __forceinline__ void cp16(uint32_t dst, const void* src, bool pred) {
    int sz = pred ? 16 : 0;   // src-size 0 -> 16B zero-fill
    asm volatile("cp.async.cg.shared.global [%0], [%1], 16, %2;"
                 :: "r"(dst), "l"(src), "r"(sz) : "memory");
}
__device__ __forceinline__ void cp_commit() { asm volatile("cp.async.commit_group;" ::: "memory"); }
template <int N>
__device__ __forceinline__ void cp_wait() { asm volatile("cp.async.wait_group %0;" :: "n"(N) : "memory"); }

__device__ __forceinline__ void ldm_x4(uint32_t* r, uint32_t addr) {
    asm volatile("ldmatrix.sync.aligned.m8n8.x4.shared.b16 {%0,%1,%2,%3}, [%4];"
                 : "=r"(r[0]), "=r"(r[1]), "=r"(r[2]), "=r"(r[3]) : "r"(addr));
}
__device__ __forceinline__ void mma16816(float* c, const uint32_t* a, const uint32_t* b) {
    asm volatile("mma.sync.aligned.m16n8k16.row.col.f32.f16.f16.f32 "
                 "{%0,%1,%2,%3}, {%4,%5,%6,%7}, {%8,%9}, {%0,%1,%2,%3};"
                 : "+f"(c[0]), "+f"(c[1]), "+f"(c[2]), "+f"(c[3])
                 : "r"(a[0]), "r"(a[1]), "r"(a[2]), "r"(a[3]), "r"(b[0]), "r"(b[1]));
}
// HW tanh (sm_75+ baseline): 1 MUFU op; sigmoid = 0.5*tanh(x/2)+0.5
__device__ __forceinline__ float tanh_ap(float x) {
    float y;
    asm("tanh.approx.f32 %0, %1;" : "=f"(y) : "f"(x));
    return y;
}
__device__ __forceinline__ float sig_ap(float x) {
    return fmaf(0.5f, tanh_ap(0.5f * x), 0.5f);
}

extern __shared__ __align__(1024) __half smem[];

// ---------------- prep kernels (fp32 weight fusion) ----------------
__global__ void prep_A(const float* __restrict__ w_ih,
                       const float* __restrict__ k0,
                       const float* __restrict__ k1) {
    __shared__ float Wt[32][33];
    __shared__ float Ks[32][33];
    int x = threadIdx.x, y = threadIdx.y;
    int gp0 = blockIdx.x * 32, kb0 = blockIdx.y * 32;
    const float* ksel = (kb0 < 256) ? k0 : k1;
    int j0 = kb0 & 255;
    float acc = 0.f;
    for (int c0 = 0; c0 < 256; c0 += 32) {
        int go = go_of_gp(gp0 + y);
        Wt[x][y] = w_ih[go * 256 + c0 + x];
        Ks[y][x] = ksel[(c0 + y) * 256 + j0 + x];
        __syncthreads();
#pragma unroll
        for (int cc = 0; cc < 32; cc++) acc += Wt[cc][x] * Ks[cc][y];
        __syncthreads();
    }
    d_AcatT[(kb0 + y) * NGO + gp0 + x] = acc;
}

__global__ void prep_W2(const float* __restrict__ w_ih,
                        const float* __restrict__ w_i2s) {
    __shared__ float Wt[32][33];
    __shared__ float Ms[32][33];
    int x = threadIdx.x, y = threadIdx.y;
    int gp0 = blockIdx.x * 32, ci0 = blockIdx.y * 32;
    float acc = 0.f;
    for (int c0 = 0; c0 < 256; c0 += 32) {
        int go = go_of_gp(gp0 + y);
        Wt[x][y] = w_ih[go * 256 + c0 + x];
        int ci = ci0 + x, c = c0 + y;
        float m = ((ci % 3) <= (c % 3)) ? 1.f : 0.f;
        Ms[y][x] = w_i2s[c * 256 + ci] * m;
        __syncthreads();
#pragma unroll
        for (int cc = 0; cc < 32; cc++) acc += Wt[cc][x] * Ms[cc][y];
        __syncthreads();
    }
    d_W2T[(ci0 + y) * NGO + gp0 + x] = acc;
}

// parallel bias fusion: 32 blocks x (32,32); warp-reduce over c
__global__ void prep_bias(const float* __restrict__ w_ih,
                          const float* __restrict__ b_ih,
                          const float* __restrict__ b_hh,
                          const float* __restrict__ b_i2s,
                          const float* __restrict__ b_s2s) {
    int gp = blockIdx.x * 32 + threadIdx.y;
    int tx = threadIdx.x;
    int go = go_of_gp(gp);
    float s = 0.f;
#pragma unroll
    for (int i = 0; i < 8; i++) {
        int c = tx * 8 + i;
        s += w_ih[go * 256 + c] * (b_i2s[c] + b_s2s[c]);
    }
#pragma unroll
    for (int o = 16; o; o >>= 1) s += __shfl_down_sync(0xffffffffu, s, o);
    if (tx == 0) d_biasT[gp] = s + b_ih[go] + b_hh[go];
}

// ---------------- fp16 packing ----------------
__global__ void pack_W() {
    int i = blockIdx.x * blockDim.x + threadIdx.x;
    if (i >= NGO * KK_STEP) return;
    int gp = i / KK_STEP, k = i % KK_STEP;
    d_Wh[i] = __float2half(d_AcatT[k * NGO + gp]);
}

__global__ void pack_W2() {
    int i = blockIdx.x * blockDim.x + threadIdx.x;
    if (i >= NGO * KK_Y) return;
    int gp = i / KK_Y, k = i % KK_Y;
    d_W2h[i] = __float2half(d_W2T[k * NGO + gp]);
}

// 4 hw-tiles per block: grid (32, 8, 16)
__global__ void pack_X(const float* __restrict__ x) {
    __shared__ float tile[4][32][33];
    int tx = threadIdx.x, ty = threadIdx.y;
    int ci0 = blockIdx.y * 32, b = blockIdx.z;
#pragma unroll
    for (int i = 0; i < 4; i++) {
        int hw0 = (blockIdx.x * 4 + i) * 32;
        tile[i][ty][tx] = x[((size_t)(b * 256 + ci0 + ty)) * 4096 + hw0 + tx];
    }
    __syncthreads();
#pragma unroll
    for (int i = 0; i < 4; i++) {
        int hw0 = (blockIdx.x * 4 + i) * 32;
        size_t row = (size_t)(b * 4096 + hw0 + ty);
        d_Xh[row * KK_Y + ci0 + tx] = __float2half(tile[i][tx][ty]);
    }
}

__global__ void init_state() {
    int i = blockIdx.x * blockDim.x + threadIdx.x;
    if (i < MROWS * NC) d_hs16[i] = __float2half(0.f);   // H slot 0
    if (i < WD * NRB) g_cnt[i] = 0;
}

// ---------------- persistent step kernel ----------------
// Grid (8,16) x 256 thr. B resident in smem; A loaded in 4 pipelined column
// groups; Y prefetched to regs before flow wait; C in regs; H stores staged
// through smem for coalescing; bias hoisted to registers.
__global__ void __launch_bounds__(256, 1) step_persist() {
    uint32_t sbase = smem_u32(smem);
    int tid = threadIdx.x;
    int lane = tid & 31, wid = tid >> 5;
    int warp_m = wid & 1, warp_n = wid >> 1;
    int n0 = blockIdx.x * 128;   // gate-col base
    int rb = blockIdx.y;         // row-block
    int r0 = rb * 128;
    uint32_t sA = sbase;
    uint32_t sB = sbase + SM_B_H * 2;
    __half* hst = smem + SM_HST_H;

    // ---- one-time B fill: 128 rows x 512 k halves ----
#pragma unroll
    for (int it = 0; it < 32; it++) {
        int u = it * 256 + tid;
        int row = u >> 6, k8 = u & 63;
        cp16(sB + (row * BLDS + k8 * 8) * 2,
             &d_Wh[(size_t)(n0 + row) * KK_STEP + k8 * 8], true);
    }
    cp_commit();
    cp_wait<0>();
    __syncthreads();

    // fixed mappings (step-invariant)
    int g4 = lane >> 2;
    bool oddl = (lane & 1);
    int rbase = r0 + warp_m * 64 + g4 + (oddl ? 8 : 0);
    int cobase = (n0 >> 2) + warp_n * 8 + ((lane >> 1) & 1);
    int rl_base = warp_m * 64 + g4 + (oddl ? 8 : 0);                 // CTA-local row
    int cl_base = warp_n * 8 + ((lane >> 1) & 1);                    // CTA-local col
    int rsel = lane & 15, hsel = lane >> 4;                          // A ldmatrix lanes
    int bn = (lane & 7), bh = (lane >> 3) & 1, btile = lane >> 4;    // B ldmatrix lanes
    bool row128_ok = ((rb & 7) != 7);   // row r0+128 valid (not a dir boundary)

    // hoist t-invariant bias into registers
    float4 bvv[4];
#pragma unroll
    for (int nt = 0; nt < 4; nt++)
        bvv[nt] = *(const float4*)&d_biasT[(cobase + nt * 2) * 4];

    float cst[4][4] = {};

    for (int t = 0; t < WD; t++) {
        const __half* Hin = d_hs16 + (size_t)t * MROWS * NC;
        __half* HO = d_hs16 + (size_t)(t + 1) * MROWS * NC;

        // ---- Y prefetch into registers (independent of H) ----
        uint2 yv[4][4];
#pragma unroll
        for (int mt = 0; mt < 4; mt++) {
            int r = rbase + mt * 16;
            int dir = r >> 10, bhv = r & 1023, bb = bhv >> 6, hh = bhv & 63;
            int dg = t - hh;
            bool has_y = (dg >= 0 && dg < 64);
            size_t ybase = 0;
            if (has_y) {
                int ww = dir ? (63 - dg) : dg;
                ybase = (size_t)((bb * 64 + hh) * 64 + ww) * NGO;
            }
#pragma unroll
            for (int nt = 0; nt < 4; nt++) {
                if (has_y) {
                    int co = cobase + nt * 2;
                    yv[mt][nt] = __ldg((const uint2*)&d_Yh[ybase + co * 4]);
                } else {
                    yv[mt][nt] = make_uint2(0u, 0u);
                }
            }
        }

        // ---- flow wait: producers of H(t) = step t-1, row-blocks rb, rb+1 ----
        if (t > 0) {
            volatile unsigned* cp0 = &g_cnt[(t - 1) * NRB + rb];
            if (tid == 0) { while (*cp0 < 8u) __nanosleep(32); }
            if (tid == 1 && rb + 1 < NRB) {
                volatile unsigned* cp1 = &g_cnt[(t - 1) * NRB + rb + 1];
                while (*cp1 < 8u) __nanosleep(32);
            }
            __syncthreads();
        }

        // ---- A load: 4 column-group commit groups (129 rows x 64 cols each) ----
#pragma unroll
        for (int g = 0; g < 4; g++) {
#pragma unroll
            for (int it = 0; it < 5; it++) {
                int u = it * 256 + tid;
                if (u < 129 * 8) {
                    int row = u >> 3, k8 = (u & 7) + 8 * g;
                    bool pred = (row < 128) || row128_ok;
                    int rg = min(r0 + row, MROWS - 1);
                    cp16(sA + (row * A_LDS + k8 * 8) * 2,
                         &Hin[(size_t)rg * NC + k8 * 8], pred);
                }
            }
            cp_commit();
        }

        // ---- mainloop: chunk pairs (j, j+4) as column group j arrives ----
        float acc[4][4][4] = {};
#pragma unroll
        for (int j = 0; j < 4; j++) {
            if (j == 0)      cp_wait<3>();
            else if (j == 1) cp_wait<2>();
            else if (j == 2) cp_wait<1>();
            else             cp_wait<0>();
            __syncthreads();
#pragma unroll
            for (int half = 0; half < 2; half++) {
                int c = j + half * 4;          // chunk index
                int row_off = half;            // shifted half reads rows+1
                int kb = j * 64;               // A column base
#pragma unroll
                for (int kc = 0; kc < 4; kc++) {
                    int kabs = c * 64 + kc * 16 + bh * 8;
                    uint32_t bfr[2][4];
#pragma unroll
                    for (int p = 0; p < 2; p++) {
                        uint32_t addr = sB + ((warp_n * 32 + p * 16 + btile * 8 + bn) * BLDS
                                              + kabs) * 2;
                        ldm_x4(bfr[p], addr);
                    }
#pragma unroll
                    for (int mt = 0; mt < 4; mt++) {
                        uint32_t af[4];
                        uint32_t addr = sA + ((row_off + warp_m * 64 + mt * 16 + rsel) * A_LDS
                                              + kb + kc * 16 + hsel * 8) * 2;
                        ldm_x4(af, addr);
#pragma unroll
                        for (int nt = 0; nt < 4; nt++)
                            mma16816(acc[mt][nt], af, &bfr[nt >> 1][(nt & 1) * 2]);
                    }
                }
            }
        }

        // ---- epilogue: pair-exchange + fused LSTM cell, stage H in smem ----
#pragma unroll
        for (int mt = 0; mt < 4; mt++) {
#pragma unroll
            for (int nt = 0; nt < 4; nt++) {
                float* a = acc[mt][nt];
                float s0 = __shfl_xor_sync(0xffffffffu, oddl ? a[0] : a[2], 1);
                float s1 = __shfl_xor_sync(0xffffffffu, oddl ? a[1] : a[3], 1);
                float gi, gf, gg, go;
                if (!oddl) { gi = a[0]; gf = a[1]; gg = s0;   go = s1;   }  // row g
                else       { gi = s0;   gf = s1;   gg = a[2]; go = a[3]; }  // row g+8
                float4 bv = bvv[nt];
                float2 y01 = __half22float2(*(__half2*)&yv[mt][nt].x);
                float2 y23 = __half22float2(*(__half2*)&yv[mt][nt].y);
                gi += bv.x + y01.x; gf += bv.y + y01.y;
                gg += bv.z + y23.x; go += bv.w + y23.y;
                float si = sig_ap(gi), sf = sig_ap(gf), so = sig_ap(go);
                float cn = sf * cst[mt][nt] + si * tanh_ap(gg);
                float hv = so * tanh_ap(cn);
                cst[mt][nt] = cn;
                hst[(rl_base + mt * 16) * HST_LDS + cl_base + nt * 2] = __float2half(hv);
            }
        }
        __syncthreads();

        // ---- coalesced H store: 128 rows x 64B ----
#pragma unroll
        for (int it = 0; it < 2; it++) {
            int u = it * 256 + tid;
            int row = u >> 2, q = u & 3;
            uint4 v = *(uint4*)&hst[row * HST_LDS + q * 8];
            *(uint4*)&HO[(size_t)(r0 + row) * NC + (n0 >> 2) + q * 8] = v;
        }

        // ---- arrive ----
        __syncthreads();
        if (tid == 0) {
            __threadfence();
            atomicAdd(&g_cnt[t * NRB + rb], 1u);
        }
    }
}

// ---------------- ygemm: d_Yh = X @ W2 (fp16 mma, 2-stage, 2 CTAs/SM) ----------------
__global__ void __launch_bounds__(256, 2) ygemm_mma() {
    uint32_t sbase = smem_u32(smem);
    int tid = threadIdx.x;
    int lane = tid & 31, wid = tid >> 5;
    int warp_m = wid & 1, warp_n = wid >> 1;
    int n0 = blockIdx.x * 128;
    int r0 = blockIdx.y * 128;

    float acc[4][4][4] = {};

    auto issue = [&](int c) {
        int buf = c % NSTAGE_Y;
        int kk0 = c * 64;
        uint32_t aoff = sbase + buf * Y_STAGE_H * 2;
        uint32_t boff = sbase + (NSTAGE_Y + buf) * Y_STAGE_H * 2;
#pragma unroll
        for (int it = 0; it < 4; it++) {
            int u = it * 256 + tid;
            int row = u >> 3, k8 = u & 7;
            cp16(aoff + (row * LDS_H + k8 * 8) * 2,
                 &d_Xh[(size_t)(r0 + row) * KK_Y + kk0 + k8 * 8], true);
        }
#pragma unroll
        for (int it = 0; it < 4; it++) {
            int u = it * 256 + tid;
            int row = u >> 3, k8 = u & 7;
            cp16(boff + (row * LDS_H + k8 * 8) * 2,
                 &d_W2h[(size_t)(n0 + row) * KK_Y + kk0 + k8 * 8], true);
        }
        cp_commit();
    };

    int rsel = lane & 15, hsel = lane >> 4;
    int bn = (lane & 7), bh = (lane >> 3) & 1, btile = lane >> 4;

    issue(0);
#pragma unroll
    for (int c = 0; c < NCH_Y; c++) {
        if (c + 1 < NCH_Y) { issue(c + 1); cp_wait<1>(); }
        else               { cp_wait<0>(); }
        __syncthreads();
        uint32_t sA = sbase + (c % NSTAGE_Y) * Y_STAGE_H * 2;
        uint32_t sB = sbase + (NSTAGE_Y + c % NSTAGE_Y) * Y_STAGE_H * 2;
#pragma unroll
        for (int kc = 0; kc < 4; kc++) {
            uint32_t bfr[2][4];
#pragma unroll
            for (int p = 0; p < 2; p++) {
                uint32_t addr = sB + ((warp_n * 32 + p * 16 + btile * 8 + bn) * LDS_H
                                      + kc * 16 + bh * 8) * 2;
                ldm_x4(bfr[p], addr);
            }
#pragma unroll
            for (int mt = 0; mt < 4; mt++) {
                uint32_t af[4];
                uint32_t addr = sA + ((warp_m * 64 + mt * 16 + rsel) * LDS_H
                                      + kc * 16 + hsel * 8) * 2;
                ldm_x4(af, addr);
#pragma unroll
                for (int nt = 0; nt < 4; nt++)
                    mma16816(acc[mt][nt], af, &bfr[nt >> 1][(nt & 1) * 2]);
            }
        }
        __syncthreads();   // protect stage reuse (2-stage: next issue writes buf c%2)
    }

    int g4 = lane >> 2;
    int col = n0 + warp_n * 32 + 2 * (lane & 3);
    int rA0 = r0 + warp_m * 64 + g4;
#pragma unroll
    for (int mt = 0; mt < 4; mt++) {
#pragma unroll
        for (int nt = 0; nt < 4; nt++) {
            float* a = acc[mt][nt];
            int cc = col + nt * 8;
            size_t pA = (size_t)(rA0 + mt * 16) * NGO + cc;
            size_t pB = (size_t)(rA0 + mt * 16 + 8) * NGO + cc;
            *(__half2*)&d_Yh[pA] = __floats2half2_rn(a[0], a[1]);
            *(__half2*)&d_Yh[pB] = __floats2half2_rn(a[2], a[3]);
        }
    }
}

// ---------------- output assembly (reads fp16 H history) ----------------
__global__ void __launch_bounds__(256) output_kernel(float* __restrict__ out) {
    __shared__ float tile[127 * 65];
    int c2 = blockIdx.x, b = blockIdx.y;
    int tid = threadIdx.x;
    int hi = c2 >> 2;
    int coL = (c2 & 3) * 64;
    int rL = b * 64 + hi;
    for (int e = tid; e < 127 * 64; e += 256) {
        int tt = e >> 6, j = e & 63;
        tile[tt * 65 + j] = __half2float(
            d_hs16[((size_t)(tt + 1) * MROWS + rL) * NC + coL + j]);
    }
    __syncthreads();
    float rl[16];
#pragma unroll
    for (int it = 0; it < 16; it++) {
        int o = it * 256 + tid;
        int h2 = o >> 6, ww = o & 63;
        rl[it] = tile[(h2 + ww) * 65 + h2];
    }
    __syncthreads();
    int rR = 1024 + b * 64 + hi;
    for (int e = tid; e < 127 * 64; e += 256) {
        int tt = e >> 6, j = e & 63;
        tile[tt * 65 + j] = __half2float(
            d_hs16[((size_t)(tt + 1) * MROWS + rR) * NC + coL + j]);
    }
    __syncthreads();
    float* ob = out + ((size_t)(b * 256 + c2)) * 64 * 64;
#pragma unroll
    for (int it = 0; it < 16; it++) {
        int o = it * 256 + tid;
        int h2 = o >> 6, ww = o & 63;
        float rv = (h2 > 0) ? tile[(h2 + 62 - ww) * 65 + (h2 - 1)] : 0.f;
        ob[o] = rl[it] + rv;
    }
}

// ---------------- launch ----------------
extern "C" void kernel_launch(void* const* d_in, const int* in_sizes, int n_in,
                              void* d_out, int out_size) {
    const float* x     = (const float*)d_in[0];
    const float* w_i2s = (const float*)d_in[1];
    const float* b_i2s = (const float*)d_in[2];
    const float* w_ih  = (const float*)d_in[3];
    const float* b_ih  = (const float*)d_in[4];
    const float* b_hh  = (const float*)d_in[5];
    const float* k0    = (const float*)d_in[6];
    const float* k1    = (const float*)d_in[7];
    const float* b_s2s = (const float*)d_in[8];
    float* out = (float*)d_out;

    cudaFuncSetAttribute(step_persist, cudaFuncAttributeMaxDynamicSharedMemorySize, SMEM_STEP);
    cudaFuncSetAttribute(ygemm_mma,    cudaFuncAttributeMaxDynamicSharedMemorySize, SMEM_Y);

    prep_A  <<<dim3(32, 16), dim3(32, 32)>>>(w_ih, k0, k1);
    prep_W2 <<<dim3(32, 8),  dim3(32, 32)>>>(w_ih, w_i2s);
    prep_bias<<<32, dim3(32, 32)>>>(w_ih, b_ih, b_hh, b_i2s, b_s2s);
    pack_W  <<<(NGO * KK_STEP + 255) / 256, 256>>>();
    pack_W2 <<<(NGO * KK_Y + 255) / 256, 256>>>();
    pack_X  <<<dim3(32, 8, 16), dim3(32, 32)>>>(x);
    init_state<<<(MROWS * NC + 255) / 256, 256>>>();

    ygemm_mma<<<dim3(8, 512), 256, SMEM_Y>>>();

    step_persist<<<dim3(8, 16), 256, SMEM_STEP>>>();

    output_kernel<<<dim3(256, 16), 256>>>(out);
}